// round 2
// baseline (speedup 1.0000x reference)
#include <cuda_runtime.h>
#include <math.h>
#include <float.h>

#define CH 256
#define NQ 4096
#define NK 3072
#define NH 8
#define HD 32

// Scratch (static device globals — no allocations allowed)
__device__ float g_Q[2 * CH * NQ];   // 8 MB
__device__ float g_K[2 * CH * NK];   // 6 MB
__device__ float g_V[2 * CH * NK];   // 6 MB
__device__ float g_A[2 * CH * NQ];   // attention output (pre o-proj)
__device__ float g_O[2 * CH * NQ];   // o-proj + residual (LN input)

// ---------------------------------------------------------------------------
// Generic 1x1-conv projection GEMM: Y[o,n] = sum_c W[o,c] * X[c,n] + bias[o]
// Tile 64x64, 256 threads, 4x4 microtile, k-tile 16. Optional residual add.
// All dims here are multiples of 64 so no guards needed.
// ---------------------------------------------------------------------------
__global__ __launch_bounds__(256) void proj_gemm(
    const float* __restrict__ W, const float* __restrict__ bias,
    const float* __restrict__ X, long xbs, int ldx,
    float* __restrict__ Y, long ybs, int ldy,
    const float* __restrict__ R, long rbs)
{
    int b = blockIdx.z;
    const float* Xb = X + (long)b * xbs;
    float* Yb = Y + (long)b * ybs;

    int n0 = blockIdx.x * 64;
    int o0 = blockIdx.y * 64;

    __shared__ float Ws[64][16];
    __shared__ float Xs[16][64];

    int tid = threadIdx.x;
    int tx = tid & 15;      // token sub-tile
    int ty = tid >> 4;      // out-channel sub-tile

    float acc[4][4] = {};

    for (int c0 = 0; c0 < CH; c0 += 16) {
        #pragma unroll
        for (int i = 0; i < 4; i++) {
            int idx = i * 256 + tid;
            Ws[idx >> 4][idx & 15] = W[(long)(o0 + (idx >> 4)) * CH + c0 + (idx & 15)];
            Xs[idx >> 6][idx & 63] = Xb[(long)(c0 + (idx >> 6)) * ldx + n0 + (idx & 63)];
        }
        __syncthreads();

        #pragma unroll
        for (int cc = 0; cc < 16; cc++) {
            float a0 = Ws[ty * 4 + 0][cc];
            float a1 = Ws[ty * 4 + 1][cc];
            float a2 = Ws[ty * 4 + 2][cc];
            float a3 = Ws[ty * 4 + 3][cc];
            float4 b4 = *reinterpret_cast<const float4*>(&Xs[cc][tx * 4]);
            acc[0][0] += a0 * b4.x; acc[0][1] += a0 * b4.y; acc[0][2] += a0 * b4.z; acc[0][3] += a0 * b4.w;
            acc[1][0] += a1 * b4.x; acc[1][1] += a1 * b4.y; acc[1][2] += a1 * b4.z; acc[1][3] += a1 * b4.w;
            acc[2][0] += a2 * b4.x; acc[2][1] += a2 * b4.y; acc[2][2] += a2 * b4.z; acc[2][3] += a2 * b4.w;
            acc[3][0] += a3 * b4.x; acc[3][1] += a3 * b4.y; acc[3][2] += a3 * b4.z; acc[3][3] += a3 * b4.w;
        }
        __syncthreads();
    }

    #pragma unroll
    for (int i = 0; i < 4; i++) {
        int o = o0 + ty * 4 + i;
        float bv = bias[o];
        #pragma unroll
        for (int j = 0; j < 4; j++) {
            int nn = n0 + tx * 4 + j;
            float v = acc[i][j] + bv;
            if (R) v += R[(long)b * rbs + (long)o * ldy + nn];
            Yb[(long)o * ldy + nn] = v;
        }
    }
}

// ---------------------------------------------------------------------------
// Flash-attention style: 1 thread = 1 query. CTA = (128 queries, head, batch).
// K/V tiles of 64 keys in smem (layout [d][k], all reads are broadcasts,
// float4-vectorized). Online softmax, fp32 accumulation.
// ---------------------------------------------------------------------------
__global__ __launch_bounds__(128) void attn_kernel()
{
    const int b = blockIdx.z;
    const int h = blockIdx.y;
    const int tid = threadIdx.x;
    const int n = blockIdx.x * 128 + tid;     // query index
    const float scale = 0.17677669529663689f; // 32^-0.5

    const float* Qp = g_Q + (long)b * CH * NQ;
    const float* Kp = g_K + (long)b * CH * NK;
    const float* Vp = g_V + (long)b * CH * NK;

    float q[HD];
    #pragma unroll
    for (int d = 0; d < HD; d++)
        q[d] = Qp[(long)(h * HD + d) * NQ + n] * scale;

    float m = -FLT_MAX;
    float l = 0.0f;
    float acc[HD];
    #pragma unroll
    for (int d = 0; d < HD; d++) acc[d] = 0.0f;

    __shared__ float Ks[HD][64];
    __shared__ float Vs[HD][64];

    #pragma unroll 1
    for (int k0 = 0; k0 < NK; k0 += 64) {
        __syncthreads();
        #pragma unroll
        for (int i = 0; i < 16; i++) {
            int idx = i * 128 + tid;     // 0..2047
            int d = idx >> 6, kk = idx & 63;
            long goff = (long)(h * HD + d) * NK + k0 + kk;
            Ks[d][kk] = Kp[goff];
            Vs[d][kk] = Vp[goff];
        }
        __syncthreads();

        #pragma unroll 1
        for (int j0 = 0; j0 < 64; j0 += 16) {
            // --- scores for 16 keys ---
            float s[16];
            #pragma unroll
            for (int jj = 0; jj < 16; jj++) s[jj] = 0.0f;
            #pragma unroll
            for (int d = 0; d < HD; d++) {
                float qd = q[d];
                const float4* kp4 = reinterpret_cast<const float4*>(&Ks[d][j0]);
                #pragma unroll
                for (int v = 0; v < 4; v++) {
                    float4 kv = kp4[v];
                    s[v * 4 + 0] += qd * kv.x;
                    s[v * 4 + 1] += qd * kv.y;
                    s[v * 4 + 2] += qd * kv.z;
                    s[v * 4 + 3] += qd * kv.w;
                }
            }
            // --- online softmax update ---
            float mt = m;
            #pragma unroll
            for (int jj = 0; jj < 16; jj++) mt = fmaxf(mt, s[jj]);
            float corr = __expf(m - mt);   // 0 on first chunk (m = -FLT_MAX)
            m = mt;
            l *= corr;
            #pragma unroll
            for (int d = 0; d < HD; d++) acc[d] *= corr;

            float p[16];
            #pragma unroll
            for (int jj = 0; jj < 16; jj++) {
                p[jj] = __expf(s[jj] - m);
                l += p[jj];
            }
            // --- PV accumulate ---
            #pragma unroll
            for (int d = 0; d < HD; d++) {
                const float4* vp4 = reinterpret_cast<const float4*>(&Vs[d][j0]);
                float a = acc[d];
                #pragma unroll
                for (int v = 0; v < 4; v++) {
                    float4 vv = vp4[v];
                    a += p[v * 4 + 0] * vv.x;
                    a += p[v * 4 + 1] * vv.y;
                    a += p[v * 4 + 2] * vv.z;
                    a += p[v * 4 + 3] * vv.w;
                }
                acc[d] = a;
            }
        }
    }

    float inv = 1.0f / l;
    float* Ap = g_A + (long)b * CH * NQ;
    #pragma unroll
    for (int d = 0; d < HD; d++)
        Ap[(long)(h * HD + d) * NQ + n] = acc[d] * inv;   // coalesced across tid
}

// ---------------------------------------------------------------------------
// LayerNorm over C for each token. Block = 32 tokens, smem transpose so both
// global reads and writes are coalesced; warp-per-token reduction.
// ---------------------------------------------------------------------------
__global__ __launch_bounds__(256) void ln_kernel(
    const float* __restrict__ lnw, const float* __restrict__ lnb,
    float* __restrict__ out)
{
    const int b = blockIdx.y;
    const int n0 = blockIdx.x * 32;
    const int tid = threadIdx.x;

    __shared__ float s[CH][33];
    __shared__ float smu[32], srs[32];

    const float* Xp = g_O + (long)b * CH * NQ;

    const int cBase = tid >> 5;   // 0..7
    const int nn = tid & 31;      // token within tile

    #pragma unroll
    for (int i = 0; i < 32; i++) {
        int c = cBase + i * 8;
        s[c][nn] = Xp[(long)c * NQ + n0 + nn];   // coalesced (32 consecutive n)
    }
    __syncthreads();

    int warp = tid >> 5, lane = tid & 31;
    for (int t = warp; t < 32; t += 8) {
        float sum = 0.0f, sq = 0.0f;
        #pragma unroll
        for (int j = 0; j < 8; j++) {
            float x = s[lane + j * 32][t];   // bank-conflict free (33 stride)
            sum += x;
            sq += x * x;
        }
        #pragma unroll
        for (int off = 16; off > 0; off >>= 1) {
            sum += __shfl_xor_sync(0xFFFFFFFF, sum, off);
            sq  += __shfl_xor_sync(0xFFFFFFFF, sq, off);
        }
        if (lane == 0) {
            float mu = sum * (1.0f / CH);
            float var = sq * (1.0f / CH) - mu * mu;
            smu[t] = mu;
            srs[t] = rsqrtf(var + 1e-5f);
        }
    }
    __syncthreads();

    float mu = smu[nn];
    float rs = srs[nn];
    #pragma unroll
    for (int i = 0; i < 32; i++) {
        int c = cBase + i * 8;
        float v = (s[c][nn] - mu) * rs * lnw[c] + lnb[c];
        out[(long)b * CH * NQ + (long)c * NQ + n0 + nn] = v;
    }
}

// ---------------------------------------------------------------------------
extern "C" void kernel_launch(void* const* d_in, const int* in_sizes, int n_in,
                              void* d_out, int out_size)
{
    const float* s3  = (const float*)d_in[0];
    const float* s4  = (const float*)d_in[1];
    const float* s5  = (const float*)d_in[2];
    const float* qw  = (const float*)d_in[3];
    const float* qb  = (const float*)d_in[4];
    const float* kw  = (const float*)d_in[5];
    const float* kb  = (const float*)d_in[6];
    const float* vw  = (const float*)d_in[7];
    const float* vb  = (const float*)d_in[8];
    const float* ow  = (const float*)d_in[9];
    const float* ob  = (const float*)d_in[10];
    const float* lnw = (const float*)d_in[11];
    const float* lnb = (const float*)d_in[12];
    float* out = (float*)d_out;

    float *Q, *K, *V, *A, *O;
    cudaGetSymbolAddress((void**)&Q, g_Q);
    cudaGetSymbolAddress((void**)&K, g_K);
    cudaGetSymbolAddress((void**)&V, g_V);
    cudaGetSymbolAddress((void**)&A, g_A);
    cudaGetSymbolAddress((void**)&O, g_O);

    dim3 blk(256);
    const long QS = (long)CH * NQ;      // per-batch stride, q-length tensors
    const long KS = (long)CH * NK;      // per-batch stride, k-length tensors

    // Q projection (from s3)
    proj_gemm<<<dim3(NQ / 64, CH / 64, 2), blk>>>(qw, qb, s3, QS, NQ, Q, QS, NQ, nullptr, 0);
    // K projection: s4 -> cols [0,2048), s5 -> cols [2048,3072)
    proj_gemm<<<dim3(2048 / 64, CH / 64, 2), blk>>>(kw, kb, s4, (long)CH * 2048, 2048, K,        KS, NK, nullptr, 0);
    proj_gemm<<<dim3(1024 / 64, CH / 64, 2), blk>>>(kw, kb, s5, (long)CH * 1024, 1024, K + 2048, KS, NK, nullptr, 0);
    // V projection
    proj_gemm<<<dim3(2048 / 64, CH / 64, 2), blk>>>(vw, vb, s4, (long)CH * 2048, 2048, V,        KS, NK, nullptr, 0);
    proj_gemm<<<dim3(1024 / 64, CH / 64, 2), blk>>>(vw, vb, s5, (long)CH * 1024, 1024, V + 2048, KS, NK, nullptr, 0);

    // Attention
    attn_kernel<<<dim3(NQ / 128, NH, 2), 128>>>();

    // Output projection + residual (s3)
    proj_gemm<<<dim3(NQ / 64, CH / 64, 2), blk>>>(ow, ob, A, QS, NQ, O, QS, NQ, s3, QS);

    // LayerNorm -> final output
    ln_kernel<<<dim3(NQ / 32, 2), 256>>>(lnw, lnb, out);
}

// round 10
// speedup vs baseline: 3.8927x; 3.8927x over previous
#include <cuda_runtime.h>
#include <cuda_bf16.h>
#include <math.h>
#include <float.h>
#include <stdint.h>

#define CH 256
#define NQ 4096
#define NK 3072
#define NH 8
#define HD 32

// ---------------- scratch (no allocations allowed) ----------------
__device__ float g_Q[2 * CH * NQ];
__device__ float g_K[2 * CH * NK];
__device__ float g_V[2 * CH * NK];
__device__ float g_A[2 * CH * NQ];
__device__ float g_O[2 * CH * NQ];
__device__ __nv_bfloat16 g_Qb[(size_t)2 * NH * NQ * HD];  // [b][h][n][d]
__device__ __nv_bfloat16 g_Kb[(size_t)2 * NH * NK * HD];  // [b][h][k][d]
__device__ __nv_bfloat16 g_Vb[(size_t)2 * CH * NK];       // [b][h*HD+d][k]

// ---------------- helpers (sm_80-level PTX only; no 'a' features) ----------
__device__ __forceinline__ uint32_t smem_u32(const void* p) {
    uint32_t a;
    asm("{ .reg .u64 t; cvta.to.shared.u64 t, %1; cvt.u32.u64 %0, t; }" : "=r"(a) : "l"(p));
    return a;
}
__device__ __forceinline__ void ldsm_x4(uint32_t* r, uint32_t addr) {
    asm volatile("ldmatrix.sync.aligned.m8n8.x4.shared.b16 {%0,%1,%2,%3}, [%4];"
        : "=r"(r[0]), "=r"(r[1]), "=r"(r[2]), "=r"(r[3]) : "r"(addr));
}
__device__ __forceinline__ void ldsm_x2(uint32_t* r, uint32_t addr) {
    asm volatile("ldmatrix.sync.aligned.m8n8.x2.shared.b16 {%0,%1}, [%2];"
        : "=r"(r[0]), "=r"(r[1]) : "r"(addr));
}
__device__ __forceinline__ void mma16816(float* c, const uint32_t* a, const uint32_t* b) {
    asm volatile(
        "mma.sync.aligned.m16n8k16.row.col.f32.bf16.bf16.f32 "
        "{%0,%1,%2,%3}, {%4,%5,%6,%7}, {%8,%9}, {%0,%1,%2,%3};"
        : "+f"(c[0]), "+f"(c[1]), "+f"(c[2]), "+f"(c[3])
        : "r"(a[0]), "r"(a[1]), "r"(a[2]), "r"(a[3]), "r"(b[0]), "r"(b[1]));
}
__device__ __forceinline__ uint32_t packbf2(float x, float y) {
    __nv_bfloat162 v = __floats2bfloat162_rn(x, y);
    return *reinterpret_cast<uint32_t*>(&v);
}

// ---------------------------------------------------------------------------
// fp32 projection GEMM (known-good from R1)
// ---------------------------------------------------------------------------
__global__ __launch_bounds__(256) void proj_gemm(
    const float* __restrict__ W, const float* __restrict__ bias,
    const float* __restrict__ X, long xbs, int ldx,
    float* __restrict__ Y, long ybs, int ldy,
    const float* __restrict__ R, long rbs)
{
    int b = blockIdx.z;
    const float* Xb = X + (long)b * xbs;
    float* Yb = Y + (long)b * ybs;
    int n0 = blockIdx.x * 64;
    int o0 = blockIdx.y * 64;

    __shared__ float Ws[64][16];
    __shared__ float Xs[16][64];
    int tid = threadIdx.x;
    int tx = tid & 15, ty = tid >> 4;
    float acc[4][4] = {};

    for (int c0 = 0; c0 < CH; c0 += 16) {
        #pragma unroll
        for (int i = 0; i < 4; i++) {
            int idx = i * 256 + tid;
            Ws[idx >> 4][idx & 15] = W[(long)(o0 + (idx >> 4)) * CH + c0 + (idx & 15)];
            Xs[idx >> 6][idx & 63] = Xb[(long)(c0 + (idx >> 6)) * ldx + n0 + (idx & 63)];
        }
        __syncthreads();
        #pragma unroll
        for (int cc = 0; cc < 16; cc++) {
            float a0 = Ws[ty * 4 + 0][cc], a1 = Ws[ty * 4 + 1][cc];
            float a2 = Ws[ty * 4 + 2][cc], a3 = Ws[ty * 4 + 3][cc];
            float4 b4 = *reinterpret_cast<const float4*>(&Xs[cc][tx * 4]);
            acc[0][0] += a0 * b4.x; acc[0][1] += a0 * b4.y; acc[0][2] += a0 * b4.z; acc[0][3] += a0 * b4.w;
            acc[1][0] += a1 * b4.x; acc[1][1] += a1 * b4.y; acc[1][2] += a1 * b4.z; acc[1][3] += a1 * b4.w;
            acc[2][0] += a2 * b4.x; acc[2][1] += a2 * b4.y; acc[2][2] += a2 * b4.z; acc[2][3] += a2 * b4.w;
            acc[3][0] += a3 * b4.x; acc[3][1] += a3 * b4.y; acc[3][2] += a3 * b4.z; acc[3][3] += a3 * b4.w;
        }
        __syncthreads();
    }
    #pragma unroll
    for (int i = 0; i < 4; i++) {
        int o = o0 + ty * 4 + i;
        float bv = bias[o];
        #pragma unroll
        for (int j = 0; j < 4; j++) {
            int nn = n0 + tx * 4 + j;
            float v = acc[i][j] + bv;
            if (R) v += R[(long)b * rbs + (long)o * ldy + nn];
            Yb[(long)o * ldy + nn] = v;
        }
    }
}

// ---------------------------------------------------------------------------
// fp32 [b][C][N] (channel-major) -> bf16 [b][h][n][32] (token-major), × scale
// ---------------------------------------------------------------------------
__global__ __launch_bounds__(256) void tconv_kernel(
    const float* __restrict__ in, __nv_bfloat16* __restrict__ out, int N, float scale)
{
    __shared__ float s[32][33];
    int b = blockIdx.z, h = blockIdx.y, n0 = blockIdx.x * 32;
    int tid = threadIdx.x;
    int a = tid >> 5, e = tid & 31;
    #pragma unroll
    for (int p = 0; p < 4; p++) {
        int d = p * 8 + a;
        s[d][e] = in[((long)b * CH + h * HD + d) * N + n0 + e];
    }
    __syncthreads();
    #pragma unroll
    for (int p = 0; p < 4; p++) {
        int t = p * 8 + a;
        out[(((long)b * NH + h) * N + n0 + t) * HD + e] = __float2bfloat16(s[e][t] * scale);
    }
}

__global__ __launch_bounds__(256) void vconv_kernel(
    const float* __restrict__ in, __nv_bfloat16* __restrict__ out, int n4)
{
    int i = blockIdx.x * blockDim.x + threadIdx.x;
    if (i < n4) {
        float4 v = reinterpret_cast<const float4*>(in)[i];
        __nv_bfloat162 a = __floats2bfloat162_rn(v.x, v.y);
        __nv_bfloat162 c = __floats2bfloat162_rn(v.z, v.w);
        uint2 u;
        u.x = *reinterpret_cast<uint32_t*>(&a);
        u.y = *reinterpret_cast<uint32_t*>(&c);
        reinterpret_cast<uint2*>(out)[i] = u;
    }
}

// ---------------------------------------------------------------------------
// HMMA (mma.sync m16n8k16 bf16) flash attention.
// CTA = 256 queries x 1 head, 8 warps; warp owns 32 query rows (2 m16 tiles).
// Stream 64-key K/V tiles through smem; 16-key chunks:
//   S = Q K^T (mma) -> exp (no max-sub) -> pack P bf16 in regs -> O += P V (mma).
// ---------------------------------------------------------------------------
#define ST_QK 40   // row stride (elems) for Q/K tiles: 80B -> ldmatrix bank-clean
#define ST_V  72   // row stride (elems) for V tile: 144B -> bank-clean

__global__ __launch_bounds__(256, 2) void attn_mma_kernel()
{
    __shared__ __nv_bfloat16 Qs[256 * ST_QK];  // 20480 B
    __shared__ __nv_bfloat16 Ks[64 * ST_QK];   //  5120 B
    __shared__ __nv_bfloat16 Vs[32 * ST_V];    //  4608 B

    const int b = blockIdx.z, h = blockIdx.y;
    const int q0 = blockIdx.x * 256;
    const int tid = threadIdx.x;
    const int wid = tid >> 5, lane = tid & 31;

    // ---- load Q tile (256 rows x 32 d), rows contiguous 64B in gmem ----
    {
        const uint4* qg = reinterpret_cast<const uint4*>(
            g_Qb + ((long)(b * NH + h) * NQ + q0) * HD);
        #pragma unroll
        for (int i = 0; i < 4; i++) {
            int idx = tid + i * 256;
            int row = idx >> 2, c = idx & 3;
            *reinterpret_cast<uint4*>(&Qs[row * ST_QK + c * 8]) = qg[idx];
        }
    }
    __syncthreads();

    // ---- persistent Q A-fragments: [mtile][kstep][4] ----
    uint32_t aq[2][2][4];
    {
        int mat = lane >> 3, r = lane & 7;
        #pragma unroll
        for (int mt = 0; mt < 2; mt++)
            #pragma unroll
            for (int ks = 0; ks < 2; ks++)
                ldsm_x4(aq[mt][ks], smem_u32(
                    &Qs[(wid * 32 + mt * 16 + (mat & 1) * 8 + r) * ST_QK
                        + ks * 16 + (mat >> 1) * 8]));
    }

    const __nv_bfloat16* Kg = g_Kb + (long)(b * NH + h) * NK * HD;
    const __nv_bfloat16* Vg = g_Vb + ((long)b * CH + h * HD) * NK;

    float o[2][4][4];
    #pragma unroll
    for (int mt = 0; mt < 2; mt++)
        #pragma unroll
        for (int dn = 0; dn < 4; dn++)
            #pragma unroll
            for (int j = 0; j < 4; j++) o[mt][dn][j] = 0.0f;
    float lsum[2][2] = {{0.0f, 0.0f}, {0.0f, 0.0f}};

    const int r8 = lane & 7;
    const int half = (lane >> 3) & 1;

    #pragma unroll 1
    for (int t = 0; t < NK / 64; t++) {
        const int k0 = t * 64;
        __syncthreads();
        // K tile: 64 rows x 32d (256 threads -> 1 uint4 each)
        {
            const uint4* kg = reinterpret_cast<const uint4*>(Kg + (long)k0 * HD);
            int row = tid >> 2, c = tid & 3;
            *reinterpret_cast<uint4*>(&Ks[row * ST_QK + c * 8]) = kg[tid];
            // V tile: 32 rows (d) x 64 keys, rows strided NK
            int vr = tid >> 3, vc = tid & 7;
            *reinterpret_cast<uint4*>(&Vs[vr * ST_V + vc * 8]) =
                *reinterpret_cast<const uint4*>(Vg + (long)vr * NK + k0 + vc * 8);
        }
        __syncthreads();

        #pragma unroll
        for (int chnk = 0; chnk < 4; chnk++) {
            const int kb = chnk * 16;

            // K B-fragments: [n8-tile][kstep][2]
            uint32_t bk[2][2][2];
            #pragma unroll
            for (int n = 0; n < 2; n++)
                #pragma unroll
                for (int ks = 0; ks < 2; ks++)
                    ldsm_x2(bk[n][ks], smem_u32(
                        &Ks[(kb + n * 8 + r8) * ST_QK + ks * 16 + half * 8]));

            // S = Q K^T
            float s[2][2][4];
            #pragma unroll
            for (int mt = 0; mt < 2; mt++)
                #pragma unroll
                for (int n = 0; n < 2; n++) {
                    #pragma unroll
                    for (int j = 0; j < 4; j++) s[mt][n][j] = 0.0f;
                    mma16816(s[mt][n], aq[mt][0], bk[n][0]);
                    mma16816(s[mt][n], aq[mt][1], bk[n][1]);
                }

            // exp + row-sum + pack P as A-fragment of the PV mma
            uint32_t ap[2][4];
            #pragma unroll
            for (int mt = 0; mt < 2; mt++) {
                float e0 = __expf(s[mt][0][0]);
                float e1 = __expf(s[mt][0][1]);
                float e2 = __expf(s[mt][0][2]);
                float e3 = __expf(s[mt][0][3]);
                float e4 = __expf(s[mt][1][0]);
                float e5 = __expf(s[mt][1][1]);
                float e6 = __expf(s[mt][1][2]);
                float e7 = __expf(s[mt][1][3]);
                lsum[mt][0] += (e0 + e1) + (e4 + e5);   // row g
                lsum[mt][1] += (e2 + e3) + (e6 + e7);   // row g+8
                ap[mt][0] = packbf2(e0, e1);
                ap[mt][1] = packbf2(e2, e3);
                ap[mt][2] = packbf2(e4, e5);
                ap[mt][3] = packbf2(e6, e7);
            }

            // V B-fragments: [d-tile][2]
            uint32_t bv[4][2];
            #pragma unroll
            for (int dn = 0; dn < 4; dn++)
                ldsm_x2(bv[dn], smem_u32(
                    &Vs[(dn * 8 + r8) * ST_V + kb + half * 8]));

            // O += P V
            #pragma unroll
            for (int mt = 0; mt < 2; mt++)
                #pragma unroll
                for (int dn = 0; dn < 4; dn++)
                    mma16816(o[mt][dn], ap[mt], bv[dn]);
        }
    }

    // reduce row sums across the 4 quad lanes
    float linv[2][2];
    #pragma unroll
    for (int mt = 0; mt < 2; mt++)
        #pragma unroll
        for (int rh = 0; rh < 2; rh++) {
            float v = lsum[mt][rh];
            v += __shfl_xor_sync(0xFFFFFFFFu, v, 1);
            v += __shfl_xor_sync(0xFFFFFFFFu, v, 2);
            linv[mt][rh] = 1.0f / v;
        }

    // store: g_A is [b][h*HD + d][n]
    float* Ap = g_A + (long)b * CH * NQ + (long)h * HD * NQ;
    const int g = lane >> 2, tg = lane & 3;
    #pragma unroll
    for (int mt = 0; mt < 2; mt++)
        #pragma unroll
        for (int dn = 0; dn < 4; dn++)
            #pragma unroll
            for (int rh = 0; rh < 2; rh++) {
                int n = q0 + wid * 32 + mt * 16 + rh * 8 + g;
                float sc = linv[mt][rh];
                int d0 = dn * 8 + tg * 2;
                Ap[(long)d0 * NQ + n]       = o[mt][dn][rh * 2 + 0] * sc;
                Ap[(long)(d0 + 1) * NQ + n] = o[mt][dn][rh * 2 + 1] * sc;
            }
}

// ---------------------------------------------------------------------------
// LayerNorm (known-good from R1)
// ---------------------------------------------------------------------------
__global__ __launch_bounds__(256) void ln_kernel(
    const float* __restrict__ lnw, const float* __restrict__ lnb,
    float* __restrict__ out)
{
    const int b = blockIdx.y;
    const int n0 = blockIdx.x * 32;
    const int tid = threadIdx.x;

    __shared__ float s[CH][33];
    __shared__ float smu[32], srs[32];

    const float* Xp = g_O + (long)b * CH * NQ;
    const int cBase = tid >> 5;
    const int nn = tid & 31;

    #pragma unroll
    for (int i = 0; i < 32; i++) {
        int c = cBase + i * 8;
        s[c][nn] = Xp[(long)c * NQ + n0 + nn];
    }
    __syncthreads();

    int warp = tid >> 5, lane = tid & 31;
    for (int t = warp; t < 32; t += 8) {
        float sum = 0.0f, sq = 0.0f;
        #pragma unroll
        for (int j = 0; j < 8; j++) {
            float x = s[lane + j * 32][t];
            sum += x; sq += x * x;
        }
        #pragma unroll
        for (int off = 16; off > 0; off >>= 1) {
            sum += __shfl_xor_sync(0xFFFFFFFF, sum, off);
            sq  += __shfl_xor_sync(0xFFFFFFFF, sq, off);
        }
        if (lane == 0) {
            float mu = sum * (1.0f / CH);
            float var = sq * (1.0f / CH) - mu * mu;
            smu[t] = mu;
            srs[t] = rsqrtf(var + 1e-5f);
        }
    }
    __syncthreads();

    float mu = smu[nn], rs = srs[nn];
    #pragma unroll
    for (int i = 0; i < 32; i++) {
        int c = cBase + i * 8;
        float v = (s[c][nn] - mu) * rs * lnw[c] + lnb[c];
        out[(long)b * CH * NQ + (long)c * NQ + n0 + nn] = v;
    }
}

// ---------------------------------------------------------------------------
extern "C" void kernel_launch(void* const* d_in, const int* in_sizes, int n_in,
                              void* d_out, int out_size)
{
    const float* s3  = (const float*)d_in[0];
    const float* s4  = (const float*)d_in[1];
    const float* s5  = (const float*)d_in[2];
    const float* qw  = (const float*)d_in[3];
    const float* qb  = (const float*)d_in[4];
    const float* kw  = (const float*)d_in[5];
    const float* kb  = (const float*)d_in[6];
    const float* vw  = (const float*)d_in[7];
    const float* vb  = (const float*)d_in[8];
    const float* ow  = (const float*)d_in[9];
    const float* ob  = (const float*)d_in[10];
    const float* lnw = (const float*)d_in[11];
    const float* lnb = (const float*)d_in[12];
    float* out = (float*)d_out;

    float *Q, *K, *V, *A, *O;
    __nv_bfloat16 *Qb, *Kb, *Vb;
    cudaGetSymbolAddress((void**)&Q, g_Q);
    cudaGetSymbolAddress((void**)&K, g_K);
    cudaGetSymbolAddress((void**)&V, g_V);
    cudaGetSymbolAddress((void**)&A, g_A);
    cudaGetSymbolAddress((void**)&O, g_O);
    cudaGetSymbolAddress((void**)&Qb, g_Qb);
    cudaGetSymbolAddress((void**)&Kb, g_Kb);
    cudaGetSymbolAddress((void**)&Vb, g_Vb);

    dim3 blk(256);
    const long QS = (long)CH * NQ;
    const long KS = (long)CH * NK;

    proj_gemm<<<dim3(NQ / 64, CH / 64, 2), blk>>>(qw, qb, s3, QS, NQ, Q, QS, NQ, nullptr, 0);
    proj_gemm<<<dim3(2048 / 64, CH / 64, 2), blk>>>(kw, kb, s4, (long)CH * 2048, 2048, K,        KS, NK, nullptr, 0);
    proj_gemm<<<dim3(1024 / 64, CH / 64, 2), blk>>>(kw, kb, s5, (long)CH * 1024, 1024, K + 2048, KS, NK, nullptr, 0);
    proj_gemm<<<dim3(2048 / 64, CH / 64, 2), blk>>>(vw, vb, s4, (long)CH * 2048, 2048, V,        KS, NK, nullptr, 0);
    proj_gemm<<<dim3(1024 / 64, CH / 64, 2), blk>>>(vw, vb, s5, (long)CH * 1024, 1024, V + 2048, KS, NK, nullptr, 0);

    // bf16 layout converts (softmax scale folded into Q)
    tconv_kernel<<<dim3(NQ / 32, NH, 2), 256>>>(Q, Qb, NQ, 0.17677669529663689f);
    tconv_kernel<<<dim3(NK / 32, NH, 2), 256>>>(K, Kb, NK, 1.0f);
    vconv_kernel<<<(2 * CH * NK / 4 + 255) / 256, 256>>>(V, Vb, 2 * CH * NK / 4);

    // HMMA flash attention
    attn_mma_kernel<<<dim3(NQ / 256, NH, 2), 256>>>();

    // output projection + residual, then LN
    proj_gemm<<<dim3(NQ / 64, CH / 64, 2), blk>>>(ow, ob, A, QS, NQ, O, QS, NQ, s3, QS);
    ln_kernel<<<dim3(NQ / 32, 2), 256>>>(lnw, lnb, out);
}

// round 11
// speedup vs baseline: 5.6024x; 1.4392x over previous
#include <cuda_runtime.h>
#include <cuda_bf16.h>
#include <math.h>
#include <float.h>
#include <stdint.h>

#define CH 256
#define NQ 4096
#define NK 3072
#define NH 8
#define HD 32

// ---------------- scratch (no allocations allowed) ----------------
__device__ float g_A[2 * CH * NQ];                        // attention out, fp32 [b][c][n]
__device__ float g_O[2 * CH * NQ];                        // o-proj + residual (LN input)
__device__ __nv_bfloat16 g_Qb[(size_t)2 * NH * NQ * HD];  // [b][h][n][d]
__device__ __nv_bfloat16 g_Kb[(size_t)2 * NH * NK * HD];  // [b][h][k][d]
__device__ __nv_bfloat16 g_Vb[(size_t)2 * NH * NK * HD];  // [b][h][k][d] (token-major now)
__device__ __nv_bfloat16 g_W[4 * CH * CH];                // bf16 weights: q,k,v,o

// ---------------- helpers (sm_80-level PTX only; no 'a' features) ----------
__device__ __forceinline__ uint32_t smem_u32(const void* p) {
    uint32_t a;
    asm("{ .reg .u64 t; cvta.to.shared.u64 t, %1; cvt.u32.u64 %0, t; }" : "=r"(a) : "l"(p));
    return a;
}
__device__ __forceinline__ void ldsm_x4(uint32_t* r, uint32_t addr) {
    asm volatile("ldmatrix.sync.aligned.m8n8.x4.shared.b16 {%0,%1,%2,%3}, [%4];"
        : "=r"(r[0]), "=r"(r[1]), "=r"(r[2]), "=r"(r[3]) : "r"(addr));
}
__device__ __forceinline__ void ldsm_x2(uint32_t* r, uint32_t addr) {
    asm volatile("ldmatrix.sync.aligned.m8n8.x2.shared.b16 {%0,%1}, [%2];"
        : "=r"(r[0]), "=r"(r[1]) : "r"(addr));
}
__device__ __forceinline__ void ldsm_x4_trans(uint32_t* r, uint32_t addr) {
    asm volatile("ldmatrix.sync.aligned.m8n8.x4.trans.shared.b16 {%0,%1,%2,%3}, [%4];"
        : "=r"(r[0]), "=r"(r[1]), "=r"(r[2]), "=r"(r[3]) : "r"(addr));
}
__device__ __forceinline__ void ldsm_x2_trans(uint32_t* r, uint32_t addr) {
    asm volatile("ldmatrix.sync.aligned.m8n8.x2.trans.shared.b16 {%0,%1}, [%2];"
        : "=r"(r[0]), "=r"(r[1]) : "r"(addr));
}
__device__ __forceinline__ void mma16816(float* c, const uint32_t* a, const uint32_t* b) {
    asm volatile(
        "mma.sync.aligned.m16n8k16.row.col.f32.bf16.bf16.f32 "
        "{%0,%1,%2,%3}, {%4,%5,%6,%7}, {%8,%9}, {%0,%1,%2,%3};"
        : "+f"(c[0]), "+f"(c[1]), "+f"(c[2]), "+f"(c[3])
        : "r"(a[0]), "r"(a[1]), "r"(a[2]), "r"(a[3]), "r"(b[0]), "r"(b[1]));
}
__device__ __forceinline__ uint32_t packbf2(float x, float y) {
    __nv_bfloat162 v = __floats2bfloat162_rn(x, y);
    return *reinterpret_cast<uint32_t*>(&v);
}

// ---------------------------------------------------------------------------
// Weight fp32 -> bf16 (all 4 weight matrices in one launch)
// ---------------------------------------------------------------------------
__global__ __launch_bounds__(256) void wconv_kernel(
    const float* __restrict__ w0, const float* __restrict__ w1,
    const float* __restrict__ w2, const float* __restrict__ w3)
{
    const float* src[4] = {w0, w1, w2, w3};
    int t = blockIdx.y;
    int i = blockIdx.x * 256 + threadIdx.x;   // float4 index, 64 blocks x 256 = CH*CH/4
    float4 v = reinterpret_cast<const float4*>(src[t])[i];
    uint2 u;
    u.x = packbf2(v.x, v.y);
    u.y = packbf2(v.z, v.w);
    reinterpret_cast<uint2*>(g_W + (size_t)t * CH * CH)[i] = u;
}

// ---------------------------------------------------------------------------
// HMMA projection: Y[o,n] = sum_c W[o,c] X[c,n] (+bias) (*scale | +residual)
// CTA = 64 tokens x 256 outs, 8 warps (warp = 16 tokens x 128 outs).
// A = X^T (fp32->bf16 in smem stage, ldmatrix trans), B = W (bf16, non-trans).
// MODE 0: write bf16 token-major [b][h][n][d] with (acc+bias)*scale
// MODE 1: write fp32 [b][c][n] with acc+bias+residual
// ---------------------------------------------------------------------------
#define STP 72

template<int MODE>
__global__ __launch_bounds__(256) void proj_hmma(
    const __nv_bfloat16* __restrict__ Wb, const float* __restrict__ bias,
    const float* __restrict__ Xg, long xbs, int ldx,
    __nv_bfloat16* __restrict__ Yb, int outN, int tokoff,
    float* __restrict__ Yf, const float* __restrict__ Rf,
    float scale)
{
    __shared__ __nv_bfloat16 Ws[256 * STP];  // 36864 B
    __shared__ __nv_bfloat16 Xs[64 * STP];   //  9216 B
    __shared__ float bs[256];

    const int b = blockIdx.y;
    const int n0 = blockIdx.x * 64;
    const int tid = threadIdx.x, lane = tid & 31, w = tid >> 5;
    const int wt = (w & 3) * 16;     // token sub-tile
    const int wo = (w >> 2) * 128;   // out-channel half
    const int r8 = lane & 7, mat = lane >> 3;

    bs[tid] = bias[tid];
    const float* Xb = Xg + (long)b * xbs;

    float acc[16][4];
    #pragma unroll
    for (int i = 0; i < 16; i++)
        #pragma unroll
        for (int j = 0; j < 4; j++) acc[i][j] = 0.0f;

    #pragma unroll 1
    for (int c0 = 0; c0 < CH; c0 += 64) {
        __syncthreads();
        // W tile: row o = tid, 64 c = 8 uint4
        {
            const uint4* wg = reinterpret_cast<const uint4*>(Wb + (long)tid * CH + c0);
            #pragma unroll
            for (int i = 0; i < 8; i++)
                *reinterpret_cast<uint4*>(&Ws[tid * STP + i * 8]) = wg[i];
        }
        // X tile: [64 c][64 n] fp32 -> bf16
        {
            #pragma unroll
            for (int i = 0; i < 4; i++) {
                int idx = tid + i * 256;
                int c = idx >> 4, n4 = idx & 15;
                float4 v = *reinterpret_cast<const float4*>(
                    Xb + (long)(c0 + c) * ldx + n0 + n4 * 4);
                uint2 u;
                u.x = packbf2(v.x, v.y);
                u.y = packbf2(v.z, v.w);
                *reinterpret_cast<uint2*>(&Xs[c * STP + n4 * 4]) = u;
            }
        }
        __syncthreads();

        #pragma unroll
        for (int ks = 0; ks < 4; ks++) {
            const int kk = ks * 16;
            uint32_t a[4];
            // A = X^T: trans load; (mat>>1) -> k8 half, (mat&1) -> tok8 half
            ldsm_x4_trans(a, smem_u32(
                &Xs[(kk + (mat >> 1) * 8 + r8) * STP + wt + (mat & 1) * 8]));
            #pragma unroll
            for (int nt = 0; nt < 8; nt++) {
                uint32_t bb[4];
                // B = W: non-trans; (mat>>1) -> n8 tile, (mat&1) -> k8 half
                ldsm_x4(bb, smem_u32(
                    &Ws[(wo + nt * 16 + (mat >> 1) * 8 + r8) * STP + kk + (mat & 1) * 8]));
                mma16816(acc[nt * 2], a, bb);
                mma16816(acc[nt * 2 + 1], a, bb + 2);
            }
        }
    }

    // epilogue: rows tok = n0 + wt + rh*8 + g, cols o = wo + n8*8 + tg*2
    const int g = lane >> 2, tg = lane & 3;
    if (MODE == 0) {
        #pragma unroll
        for (int n8 = 0; n8 < 16; n8++) {
            int o = wo + n8 * 8 + tg * 2;
            int h = o >> 5, d = o & 31;
            float b0 = bs[o], b1 = bs[o + 1];
            #pragma unroll
            for (int rh = 0; rh < 2; rh++) {
                int n = tokoff + n0 + wt + rh * 8 + g;
                uint32_t pk = packbf2((acc[n8][rh * 2] + b0) * scale,
                                      (acc[n8][rh * 2 + 1] + b1) * scale);
                *reinterpret_cast<uint32_t*>(
                    Yb + (((long)(b * NH + h) * outN + n) * HD + d)) = pk;
            }
        }
    } else {
        #pragma unroll
        for (int n8 = 0; n8 < 16; n8++) {
            int o = wo + n8 * 8 + tg * 2;
            float b0 = bs[o], b1 = bs[o + 1];
            #pragma unroll
            for (int rh = 0; rh < 2; rh++) {
                int n = n0 + wt + rh * 8 + g;
                long i0 = ((long)b * CH + o) * NQ + n;
                Yf[i0]      = acc[n8][rh * 2]     + b0 + Rf[i0];
                Yf[i0 + NQ] = acc[n8][rh * 2 + 1] + b1 + Rf[i0 + NQ];
            }
        }
    }
}

// ---------------------------------------------------------------------------
// HMMA flash attention (proven R10 core). V now token-major like K; PV B
// fragments via ldmatrix.trans (canonical FA2 pattern).
// ---------------------------------------------------------------------------
#define ST_QK 40   // 80B rows -> ldmatrix bank-clean

__global__ __launch_bounds__(256, 2) void attn_mma_kernel()
{
    __shared__ __nv_bfloat16 Qs[256 * ST_QK];  // 20480 B
    __shared__ __nv_bfloat16 Ks[64 * ST_QK];   //  5120 B
    __shared__ __nv_bfloat16 Vs[64 * ST_QK];   //  5120 B

    const int b = blockIdx.z, h = blockIdx.y;
    const int q0 = blockIdx.x * 256;
    const int tid = threadIdx.x;
    const int wid = tid >> 5, lane = tid & 31;

    // ---- load Q tile (256 rows x 32 d), rows contiguous 64B in gmem ----
    {
        const uint4* qg = reinterpret_cast<const uint4*>(
            g_Qb + ((long)(b * NH + h) * NQ + q0) * HD);
        #pragma unroll
        for (int i = 0; i < 4; i++) {
            int idx = tid + i * 256;
            int row = idx >> 2, c = idx & 3;
            *reinterpret_cast<uint4*>(&Qs[row * ST_QK + c * 8]) = qg[idx];
        }
    }
    __syncthreads();

    // ---- persistent Q A-fragments: [mtile][kstep][4] ----
    uint32_t aq[2][2][4];
    {
        int mat = lane >> 3, r = lane & 7;
        #pragma unroll
        for (int mt = 0; mt < 2; mt++)
            #pragma unroll
            for (int ks = 0; ks < 2; ks++)
                ldsm_x4(aq[mt][ks], smem_u32(
                    &Qs[(wid * 32 + mt * 16 + (mat & 1) * 8 + r) * ST_QK
                        + ks * 16 + (mat >> 1) * 8]));
    }

    const __nv_bfloat16* Kg = g_Kb + (long)(b * NH + h) * NK * HD;
    const __nv_bfloat16* Vg = g_Vb + (long)(b * NH + h) * NK * HD;

    float o[2][4][4];
    #pragma unroll
    for (int mt = 0; mt < 2; mt++)
        #pragma unroll
        for (int dn = 0; dn < 4; dn++)
            #pragma unroll
            for (int j = 0; j < 4; j++) o[mt][dn][j] = 0.0f;
    float lsum[2][2] = {{0.0f, 0.0f}, {0.0f, 0.0f}};

    const int r8 = lane & 7;
    const int half = (lane >> 3) & 1;

    #pragma unroll 1
    for (int t = 0; t < NK / 64; t++) {
        const int k0 = t * 64;
        __syncthreads();
        // K and V tiles: 64 rows x 32 d each (same layout)
        {
            const uint4* kg = reinterpret_cast<const uint4*>(Kg + (long)k0 * HD);
            const uint4* vg = reinterpret_cast<const uint4*>(Vg + (long)k0 * HD);
            int row = tid >> 2, c = tid & 3;
            *reinterpret_cast<uint4*>(&Ks[row * ST_QK + c * 8]) = kg[tid];
            *reinterpret_cast<uint4*>(&Vs[row * ST_QK + c * 8]) = vg[tid];
        }
        __syncthreads();

        #pragma unroll
        for (int chnk = 0; chnk < 4; chnk++) {
            const int kb = chnk * 16;

            // K B-fragments: [n8-tile][kstep][2]
            uint32_t bk[2][2][2];
            #pragma unroll
            for (int n = 0; n < 2; n++)
                #pragma unroll
                for (int ks = 0; ks < 2; ks++)
                    ldsm_x2(bk[n][ks], smem_u32(
                        &Ks[(kb + n * 8 + r8) * ST_QK + ks * 16 + half * 8]));

            // S = Q K^T
            float s[2][2][4];
            #pragma unroll
            for (int mt = 0; mt < 2; mt++)
                #pragma unroll
                for (int n = 0; n < 2; n++) {
                    #pragma unroll
                    for (int j = 0; j < 4; j++) s[mt][n][j] = 0.0f;
                    mma16816(s[mt][n], aq[mt][0], bk[n][0]);
                    mma16816(s[mt][n], aq[mt][1], bk[n][1]);
                }

            // exp + row-sum + pack P as A-fragment of the PV mma
            uint32_t ap[2][4];
            #pragma unroll
            for (int mt = 0; mt < 2; mt++) {
                float e0 = __expf(s[mt][0][0]);
                float e1 = __expf(s[mt][0][1]);
                float e2 = __expf(s[mt][0][2]);
                float e3 = __expf(s[mt][0][3]);
                float e4 = __expf(s[mt][1][0]);
                float e5 = __expf(s[mt][1][1]);
                float e6 = __expf(s[mt][1][2]);
                float e7 = __expf(s[mt][1][3]);
                lsum[mt][0] += (e0 + e1) + (e4 + e5);
                lsum[mt][1] += (e2 + e3) + (e6 + e7);
                ap[mt][0] = packbf2(e0, e1);
                ap[mt][1] = packbf2(e2, e3);
                ap[mt][2] = packbf2(e4, e5);
                ap[mt][3] = packbf2(e6, e7);
            }

            // V B-fragments via trans: storage [key][d] -> B[n=d][k=keys]
            uint32_t bv[4][2];
            #pragma unroll
            for (int dn = 0; dn < 4; dn++)
                ldsm_x2_trans(bv[dn], smem_u32(
                    &Vs[(kb + half * 8 + r8) * ST_QK + dn * 8]));

            // O += P V
            #pragma unroll
            for (int mt = 0; mt < 2; mt++)
                #pragma unroll
                for (int dn = 0; dn < 4; dn++)
                    mma16816(o[mt][dn], ap[mt], bv[dn]);
        }
    }

    // reduce row sums across the 4 quad lanes
    float linv[2][2];
    #pragma unroll
    for (int mt = 0; mt < 2; mt++)
        #pragma unroll
        for (int rh = 0; rh < 2; rh++) {
            float v = lsum[mt][rh];
            v += __shfl_xor_sync(0xFFFFFFFFu, v, 1);
            v += __shfl_xor_sync(0xFFFFFFFFu, v, 2);
            linv[mt][rh] = 1.0f / v;
        }

    // store: g_A is [b][h*HD + d][n]
    float* Ap = g_A + (long)b * CH * NQ + (long)h * HD * NQ;
    const int g = lane >> 2, tg = lane & 3;
    #pragma unroll
    for (int mt = 0; mt < 2; mt++)
        #pragma unroll
        for (int dn = 0; dn < 4; dn++)
            #pragma unroll
            for (int rh = 0; rh < 2; rh++) {
                int n = q0 + wid * 32 + mt * 16 + rh * 8 + g;
                float sc = linv[mt][rh];
                int d0 = dn * 8 + tg * 2;
                Ap[(long)d0 * NQ + n]       = o[mt][dn][rh * 2 + 0] * sc;
                Ap[(long)(d0 + 1) * NQ + n] = o[mt][dn][rh * 2 + 1] * sc;
            }
}

// ---------------------------------------------------------------------------
// LayerNorm (known-good)
// ---------------------------------------------------------------------------
__global__ __launch_bounds__(256) void ln_kernel(
    const float* __restrict__ lnw, const float* __restrict__ lnb,
    float* __restrict__ out)
{
    const int b = blockIdx.y;
    const int n0 = blockIdx.x * 32;
    const int tid = threadIdx.x;

    __shared__ float s[CH][33];
    __shared__ float smu[32], srs[32];

    const float* Xp = g_O + (long)b * CH * NQ;
    const int cBase = tid >> 5;
    const int nn = tid & 31;

    #pragma unroll
    for (int i = 0; i < 32; i++) {
        int c = cBase + i * 8;
        s[c][nn] = Xp[(long)c * NQ + n0 + nn];
    }
    __syncthreads();

    int warp = tid >> 5, lane = tid & 31;
    for (int t = warp; t < 32; t += 8) {
        float sum = 0.0f, sq = 0.0f;
        #pragma unroll
        for (int j = 0; j < 8; j++) {
            float x = s[lane + j * 32][t];
            sum += x; sq += x * x;
        }
        #pragma unroll
        for (int off = 16; off > 0; off >>= 1) {
            sum += __shfl_xor_sync(0xFFFFFFFF, sum, off);
            sq  += __shfl_xor_sync(0xFFFFFFFF, sq, off);
        }
        if (lane == 0) {
            float mu = sum * (1.0f / CH);
            float var = sq * (1.0f / CH) - mu * mu;
            smu[t] = mu;
            srs[t] = rsqrtf(var + 1e-5f);
        }
    }
    __syncthreads();

    float mu = smu[nn], rs = srs[nn];
    #pragma unroll
    for (int i = 0; i < 32; i++) {
        int c = cBase + i * 8;
        float v = (s[c][nn] - mu) * rs * lnw[c] + lnb[c];
        out[(long)b * CH * NQ + (long)c * NQ + n0 + nn] = v;
    }
}

// ---------------------------------------------------------------------------
extern "C" void kernel_launch(void* const* d_in, const int* in_sizes, int n_in,
                              void* d_out, int out_size)
{
    const float* s3  = (const float*)d_in[0];
    const float* s4  = (const float*)d_in[1];
    const float* s5  = (const float*)d_in[2];
    const float* qw  = (const float*)d_in[3];
    const float* qb  = (const float*)d_in[4];
    const float* kw  = (const float*)d_in[5];
    const float* kb  = (const float*)d_in[6];
    const float* vw  = (const float*)d_in[7];
    const float* vb  = (const float*)d_in[8];
    const float* ow  = (const float*)d_in[9];
    const float* ob  = (const float*)d_in[10];
    const float* lnw = (const float*)d_in[11];
    const float* lnb = (const float*)d_in[12];
    float* out = (float*)d_out;

    float *A, *O;
    __nv_bfloat16 *Qb, *Kb, *Vb, *W;
    cudaGetSymbolAddress((void**)&A, g_A);
    cudaGetSymbolAddress((void**)&O, g_O);
    cudaGetSymbolAddress((void**)&Qb, g_Qb);
    cudaGetSymbolAddress((void**)&Kb, g_Kb);
    cudaGetSymbolAddress((void**)&Vb, g_Vb);
    cudaGetSymbolAddress((void**)&W, g_W);

    const float qscale = 0.17677669529663689f;   // 32^-0.5
    const long QS = (long)CH * NQ;

    // weights -> bf16 (order: q, k, v, o)
    wconv_kernel<<<dim3(CH * CH / 1024, 4), 256>>>(qw, kw, vw, ow);

    // projections (HMMA, fused bias+scale+layout)
    proj_hmma<0><<<dim3(NQ / 64, 2), 256>>>(W,              qb, s3, QS, NQ,
                                            Qb, NQ, 0,    nullptr, nullptr, qscale);
    proj_hmma<0><<<dim3(2048 / 64, 2), 256>>>(W + CH * CH,  kb, s4, (long)CH * 2048, 2048,
                                            Kb, NK, 0,    nullptr, nullptr, 1.0f);
    proj_hmma<0><<<dim3(1024 / 64, 2), 256>>>(W + CH * CH,  kb, s5, (long)CH * 1024, 1024,
                                            Kb, NK, 2048, nullptr, nullptr, 1.0f);
    proj_hmma<0><<<dim3(2048 / 64, 2), 256>>>(W + 2 * CH * CH, vb, s4, (long)CH * 2048, 2048,
                                            Vb, NK, 0,    nullptr, nullptr, 1.0f);
    proj_hmma<0><<<dim3(1024 / 64, 2), 256>>>(W + 2 * CH * CH, vb, s5, (long)CH * 1024, 1024,
                                            Vb, NK, 2048, nullptr, nullptr, 1.0f);

    // HMMA flash attention -> g_A fp32 [b][c][n]
    attn_mma_kernel<<<dim3(NQ / 256, NH, 2), 256>>>();

    // output projection + bias + residual -> g_O, then LN
    proj_hmma<1><<<dim3(NQ / 64, 2), 256>>>(W + 3 * CH * CH, ob, A, QS, NQ,
                                            nullptr, 0, 0, O, s3, 1.0f);
    ln_kernel<<<dim3(NQ / 32, 2), 256>>>(lnw, lnb, out);
}

// round 13
// speedup vs baseline: 6.7401x; 1.2031x over previous
#include <cuda_runtime.h>
#include <cuda_bf16.h>
#include <math.h>
#include <float.h>
#include <stdint.h>

#define CH 256
#define NQ 4096
#define NK 3072
#define NH 8
#define HD 32

// ---------------- scratch (no allocations allowed) ----------------
__device__ float g_A[2 * CH * NQ];                        // attention out, fp32 [b][c][n]
__device__ float g_O[2 * CH * NQ];                        // o-proj + residual (LN input)
__device__ __nv_bfloat16 g_Qb[(size_t)2 * NH * NQ * HD];  // [b][h][n][d]
__device__ __nv_bfloat16 g_Kb[(size_t)2 * NH * NK * HD];  // [b][h][k][d]
__device__ __nv_bfloat16 g_Vb[(size_t)2 * NH * NK * HD];  // [b][h][k][d]
__device__ __nv_bfloat16 g_W[4 * CH * CH];                // bf16 weights: q,k,v,o

// ---------------- helpers (sm_80-level PTX only; no 'a' features) ----------
__device__ __forceinline__ uint32_t smem_u32(const void* p) {
    uint32_t a;
    asm("{ .reg .u64 t; cvta.to.shared.u64 t, %1; cvt.u32.u64 %0, t; }" : "=r"(a) : "l"(p));
    return a;
}
__device__ __forceinline__ void ldsm_x4(uint32_t* r, uint32_t addr) {
    asm volatile("ldmatrix.sync.aligned.m8n8.x4.shared.b16 {%0,%1,%2,%3}, [%4];"
        : "=r"(r[0]), "=r"(r[1]), "=r"(r[2]), "=r"(r[3]) : "r"(addr));
}
__device__ __forceinline__ void ldsm_x2(uint32_t* r, uint32_t addr) {
    asm volatile("ldmatrix.sync.aligned.m8n8.x2.shared.b16 {%0,%1}, [%2];"
        : "=r"(r[0]), "=r"(r[1]) : "r"(addr));
}
__device__ __forceinline__ void ldsm_x4_trans(uint32_t* r, uint32_t addr) {
    asm volatile("ldmatrix.sync.aligned.m8n8.x4.trans.shared.b16 {%0,%1,%2,%3}, [%4];"
        : "=r"(r[0]), "=r"(r[1]), "=r"(r[2]), "=r"(r[3]) : "r"(addr));
}
__device__ __forceinline__ void ldsm_x2_trans(uint32_t* r, uint32_t addr) {
    asm volatile("ldmatrix.sync.aligned.m8n8.x2.trans.shared.b16 {%0,%1}, [%2];"
        : "=r"(r[0]), "=r"(r[1]) : "r"(addr));
}
__device__ __forceinline__ void mma16816(float* c, const uint32_t* a, const uint32_t* b) {
    asm volatile(
        "mma.sync.aligned.m16n8k16.row.col.f32.bf16.bf16.f32 "
        "{%0,%1,%2,%3}, {%4,%5,%6,%7}, {%8,%9}, {%0,%1,%2,%3};"
        : "+f"(c[0]), "+f"(c[1]), "+f"(c[2]), "+f"(c[3])
        : "r"(a[0]), "r"(a[1]), "r"(a[2]), "r"(a[3]), "r"(b[0]), "r"(b[1]));
}
__device__ __forceinline__ uint32_t packbf2(float x, float y) {
    __nv_bfloat162 v = __floats2bfloat162_rn(x, y);
    return *reinterpret_cast<uint32_t*>(&v);
}
__device__ __forceinline__ void cp_async16(uint32_t dst, const void* src) {
    asm volatile("cp.async.cg.shared.global [%0], [%1], 16;" :: "r"(dst), "l"(src));
}
#define CP_COMMIT() asm volatile("cp.async.commit_group;" ::: "memory")
#define CP_WAIT0()  asm volatile("cp.async.wait_group 0;" ::: "memory")

// ---------------------------------------------------------------------------
// Weight fp32 -> bf16 (all 4 weight matrices in one launch)
// ---------------------------------------------------------------------------
__global__ __launch_bounds__(256) void wconv_kernel(
    const float* __restrict__ w0, const float* __restrict__ w1,
    const float* __restrict__ w2, const float* __restrict__ w3)
{
    const float* src[4] = {w0, w1, w2, w3};
    int t = blockIdx.y;
    int i = blockIdx.x * 256 + threadIdx.x;
    float4 v = reinterpret_cast<const float4*>(src[t])[i];
    uint2 u;
    u.x = packbf2(v.x, v.y);
    u.y = packbf2(v.z, v.w);
    reinterpret_cast<uint2*>(g_W + (size_t)t * CH * CH)[i] = u;
}

// ---------------------------------------------------------------------------
// Fused QKV projection, single launch. CTA = 128 thr, tile 32 tok x 128 outs.
// blockIdx.x in [0,320): instance+token-tile; .y = out-half; .z = batch.
// Epilogue: (acc+bias)*scale -> bf16 token-major [b][h][n][d].
// ---------------------------------------------------------------------------
#define STW 72   // Ws row stride (144B) -> ldsm bank-clean
#define STX 40   // Xs row stride (80B)  -> ldsm-trans bank-clean

__global__ __launch_bounds__(128) void proj_qkv(
    const float* __restrict__ s3, const float* __restrict__ s4,
    const float* __restrict__ s5,
    const float* __restrict__ qb2, const float* __restrict__ kb2,
    const float* __restrict__ vb2, float qsc)
{
    __shared__ __nv_bfloat16 Ws[128 * STW];  // 18432 B
    __shared__ __nv_bfloat16 Xs[64 * STX];   //  5120 B
    __shared__ float bs[128];

    const int i = blockIdx.x, oh = blockIdx.y, bb = blockIdx.z;

    const float* X; const float* bias; const __nv_bfloat16* Wsrc;
    __nv_bfloat16* dst; int ldx, outN, tokoff, tok0; float scale;
    if (i < 128)      { X = s3 + (long)bb * CH * NQ;   ldx = NQ;   tok0 = i * 32;
                        Wsrc = g_W;              bias = qb2; dst = g_Qb; outN = NQ; tokoff = 0;    scale = qsc; }
    else if (i < 192) { X = s4 + (long)bb * CH * 2048; ldx = 2048; tok0 = (i - 128) * 32;
                        Wsrc = g_W + CH * CH;    bias = kb2; dst = g_Kb; outN = NK; tokoff = 0;    scale = 1.0f; }
    else if (i < 224) { X = s5 + (long)bb * CH * 1024; ldx = 1024; tok0 = (i - 192) * 32;
                        Wsrc = g_W + CH * CH;    bias = kb2; dst = g_Kb; outN = NK; tokoff = 2048; scale = 1.0f; }
    else if (i < 288) { X = s4 + (long)bb * CH * 2048; ldx = 2048; tok0 = (i - 224) * 32;
                        Wsrc = g_W + 2 * CH * CH; bias = vb2; dst = g_Vb; outN = NK; tokoff = 0;    scale = 1.0f; }
    else              { X = s5 + (long)bb * CH * 1024; ldx = 1024; tok0 = (i - 288) * 32;
                        Wsrc = g_W + 2 * CH * CH; bias = vb2; dst = g_Vb; outN = NK; tokoff = 2048; scale = 1.0f; }

    const int tid = threadIdx.x, lane = tid & 31, w = tid >> 5;
    const int wt = (w & 1) * 16;     // token sub-tile
    const int wo = (w >> 1) * 64;    // out sub-tile
    const int r8 = lane & 7, mat = lane >> 3;

    bs[tid] = bias[oh * 128 + tid];

    float acc[8][4];
    #pragma unroll
    for (int a = 0; a < 8; a++)
        #pragma unroll
        for (int j = 0; j < 4; j++) acc[a][j] = 0.0f;

    #pragma unroll 1
    for (int c0 = 0; c0 < CH; c0 += 64) {
        __syncthreads();
        // W tile: thread row = oh*128 + tid, 64 c = 8 uint4
        {
            const uint4* wg = reinterpret_cast<const uint4*>(
                Wsrc + (long)(oh * 128 + tid) * CH + c0);
            #pragma unroll
            for (int j = 0; j < 8; j++)
                *reinterpret_cast<uint4*>(&Ws[tid * STW + j * 8]) = wg[j];
        }
        // X tile [64 c][32 tok] fp32 -> bf16
        {
            #pragma unroll
            for (int j = 0; j < 4; j++) {
                int idx = tid + j * 128;          // 0..511 float4-slots
                int c = idx >> 3, t4 = idx & 7;
                float4 v = *reinterpret_cast<const float4*>(
                    X + (long)(c0 + c) * ldx + tok0 + t4 * 4);
                uint2 u;
                u.x = packbf2(v.x, v.y);
                u.y = packbf2(v.z, v.w);
                *reinterpret_cast<uint2*>(&Xs[c * STX + t4 * 4]) = u;
            }
        }
        __syncthreads();

        #pragma unroll
        for (int ks = 0; ks < 4; ks++) {
            const int kk = ks * 16;
            uint32_t a[4];
            ldsm_x4_trans(a, smem_u32(
                &Xs[(kk + (mat >> 1) * 8 + r8) * STX + wt + (mat & 1) * 8]));
            #pragma unroll
            for (int nt = 0; nt < 4; nt++) {
                uint32_t bbf[4];
                ldsm_x4(bbf, smem_u32(
                    &Ws[(wo + nt * 16 + (mat >> 1) * 8 + r8) * STW + kk + (mat & 1) * 8]));
                mma16816(acc[nt * 2], a, bbf);
                mma16816(acc[nt * 2 + 1], a, bbf + 2);
            }
        }
    }

    // epilogue: token-major bf16, pairs along d
    const int g = lane >> 2, tg = lane & 3;
    #pragma unroll
    for (int n8 = 0; n8 < 8; n8++) {
        int ol = wo + n8 * 8 + tg * 2;       // local out 0..127
        int o = oh * 128 + ol;
        int h = o >> 5, d = o & 31;
        float b0 = bs[ol], b1 = bs[ol + 1];
        #pragma unroll
        for (int rh = 0; rh < 2; rh++) {
            int n = tokoff + tok0 + wt + rh * 8 + g;
            uint32_t pk = packbf2((acc[n8][rh * 2] + b0) * scale,
                                  (acc[n8][rh * 2 + 1] + b1) * scale);
            *reinterpret_cast<uint32_t*>(
                dst + (((long)(bb * NH + h) * outN + n) * HD + d)) = pk;
        }
    }
}

// ---------------------------------------------------------------------------
// Output projection: g_O = W_o @ g_A + bias + residual(s3), fp32 out.
// Same tiling as proj_qkv. grid = (128, 2, 2).
// ---------------------------------------------------------------------------
__global__ __launch_bounds__(128) void proj_o(
    const float* __restrict__ ob2, const float* __restrict__ res)
{
    __shared__ __nv_bfloat16 Ws[128 * STW];
    __shared__ __nv_bfloat16 Xs[64 * STX];
    __shared__ float bs[128];

    const int i = blockIdx.x, oh = blockIdx.y, bb = blockIdx.z;
    const int tok0 = i * 32;
    const float* X = g_A + (long)bb * CH * NQ;
    const __nv_bfloat16* Wsrc = g_W + 3 * CH * CH;

    const int tid = threadIdx.x, lane = tid & 31, w = tid >> 5;
    const int wt = (w & 1) * 16;
    const int wo = (w >> 1) * 64;
    const int r8 = lane & 7, mat = lane >> 3;

    bs[tid] = ob2[oh * 128 + tid];

    float acc[8][4];
    #pragma unroll
    for (int a = 0; a < 8; a++)
        #pragma unroll
        for (int j = 0; j < 4; j++) acc[a][j] = 0.0f;

    #pragma unroll 1
    for (int c0 = 0; c0 < CH; c0 += 64) {
        __syncthreads();
        {
            const uint4* wg = reinterpret_cast<const uint4*>(
                Wsrc + (long)(oh * 128 + tid) * CH + c0);
            #pragma unroll
            for (int j = 0; j < 8; j++)
                *reinterpret_cast<uint4*>(&Ws[tid * STW + j * 8]) = wg[j];
        }
        {
            #pragma unroll
            for (int j = 0; j < 4; j++) {
                int idx = tid + j * 128;
                int c = idx >> 3, t4 = idx & 7;
                float4 v = *reinterpret_cast<const float4*>(
                    X + (long)(c0 + c) * NQ + tok0 + t4 * 4);
                uint2 u;
                u.x = packbf2(v.x, v.y);
                u.y = packbf2(v.z, v.w);
                *reinterpret_cast<uint2*>(&Xs[c * STX + t4 * 4]) = u;
            }
        }
        __syncthreads();

        #pragma unroll
        for (int ks = 0; ks < 4; ks++) {
            const int kk = ks * 16;
            uint32_t a[4];
            ldsm_x4_trans(a, smem_u32(
                &Xs[(kk + (mat >> 1) * 8 + r8) * STX + wt + (mat & 1) * 8]));
            #pragma unroll
            for (int nt = 0; nt < 4; nt++) {
                uint32_t bbf[4];
                ldsm_x4(bbf, smem_u32(
                    &Ws[(wo + nt * 16 + (mat >> 1) * 8 + r8) * STW + kk + (mat & 1) * 8]));
                mma16816(acc[nt * 2], a, bbf);
                mma16816(acc[nt * 2 + 1], a, bbf + 2);
            }
        }
    }

    const int g = lane >> 2, tg = lane & 3;
    #pragma unroll
    for (int n8 = 0; n8 < 8; n8++) {
        int ol = wo + n8 * 8 + tg * 2;
        int o = oh * 128 + ol;
        float b0 = bs[ol], b1 = bs[ol + 1];
        #pragma unroll
        for (int rh = 0; rh < 2; rh++) {
            int n = tok0 + wt + rh * 8 + g;
            long i0 = ((long)bb * CH + o) * NQ + n;
            g_O[i0]      = acc[n8][rh * 2]     + b0 + res[(long)bb * CH * NQ + (long)o * NQ + n];
            g_O[i0 + NQ] = acc[n8][rh * 2 + 1] + b1 + res[(long)bb * CH * NQ + (long)(o + 1) * NQ + n];
        }
    }
}

// ---------------------------------------------------------------------------
// HMMA flash attention, cp.async double-buffered K/V, exp2-based softmax
// (log2(e)*scale folded into Q at projection time).
// ---------------------------------------------------------------------------
#define ST_QK 40   // 80B rows -> ldmatrix bank-clean

__global__ __launch_bounds__(256, 2) void attn_mma_kernel()
{
    __shared__ __nv_bfloat16 Qs[256 * ST_QK];     // 20480 B
    __shared__ __nv_bfloat16 Ks[2][64 * ST_QK];   // 10240 B
    __shared__ __nv_bfloat16 Vs[2][64 * ST_QK];   // 10240 B

    const int b = blockIdx.z, h = blockIdx.y;
    const int q0 = blockIdx.x * 256;
    const int tid = threadIdx.x;
    const int wid = tid >> 5, lane = tid & 31;

    const __nv_bfloat16* Kg = g_Kb + (long)(b * NH + h) * NK * HD;
    const __nv_bfloat16* Vg = g_Vb + (long)(b * NH + h) * NK * HD;

    const int ldrow = tid >> 2, ldc = tid & 3;   // K/V tile load mapping

    // prefetch tile 0 (K and V)
    cp_async16(smem_u32(&Ks[0][ldrow * ST_QK + ldc * 8]),
               Kg + (long)ldrow * HD + ldc * 8);
    cp_async16(smem_u32(&Vs[0][ldrow * ST_QK + ldc * 8]),
               Vg + (long)ldrow * HD + ldc * 8);
    CP_COMMIT();

    // ---- load Q tile (256 rows x 32 d) ----
    {
        const uint4* qg = reinterpret_cast<const uint4*>(
            g_Qb + ((long)(b * NH + h) * NQ + q0) * HD);
        #pragma unroll
        for (int i = 0; i < 4; i++) {
            int idx = tid + i * 256;
            int row = idx >> 2, c = idx & 3;
            *reinterpret_cast<uint4*>(&Qs[row * ST_QK + c * 8]) = qg[idx];
        }
    }
    __syncthreads();

    // ---- persistent Q A-fragments ----
    uint32_t aq[2][2][4];
    {
        int mat = lane >> 3, r = lane & 7;
        #pragma unroll
        for (int mt = 0; mt < 2; mt++)
            #pragma unroll
            for (int ks = 0; ks < 2; ks++)
                ldsm_x4(aq[mt][ks], smem_u32(
                    &Qs[(wid * 32 + mt * 16 + (mat & 1) * 8 + r) * ST_QK
                        + ks * 16 + (mat >> 1) * 8]));
    }

    float o[2][4][4];
    #pragma unroll
    for (int mt = 0; mt < 2; mt++)
        #pragma unroll
        for (int dn = 0; dn < 4; dn++)
            #pragma unroll
            for (int j = 0; j < 4; j++) o[mt][dn][j] = 0.0f;
    float lsum[2][2] = {{0.0f, 0.0f}, {0.0f, 0.0f}};

    const int r8 = lane & 7;
    const int half = (lane >> 3) & 1;
    const int NT = NK / 64;

    #pragma unroll 1
    for (int t = 0; t < NT; t++) {
        CP_WAIT0();
        __syncthreads();
        // prefetch next tile into the other buffer
        if (t + 1 < NT) {
            const int nb = (t + 1) & 1;
            const long koff = (long)(t + 1) * 64 * HD;
            cp_async16(smem_u32(&Ks[nb][ldrow * ST_QK + ldc * 8]),
                       Kg + koff + (long)ldrow * HD + ldc * 8);
            cp_async16(smem_u32(&Vs[nb][ldrow * ST_QK + ldc * 8]),
                       Vg + koff + (long)ldrow * HD + ldc * 8);
            CP_COMMIT();
        }
        const __nv_bfloat16* Kt = Ks[t & 1];
        const __nv_bfloat16* Vt = Vs[t & 1];

        #pragma unroll
        for (int chnk = 0; chnk < 4; chnk++) {
            const int kb = chnk * 16;

            uint32_t bk[2][2][2];
            #pragma unroll
            for (int n = 0; n < 2; n++)
                #pragma unroll
                for (int ks = 0; ks < 2; ks++)
                    ldsm_x2(bk[n][ks], smem_u32(
                        &Kt[(kb + n * 8 + r8) * ST_QK + ks * 16 + half * 8]));

            float s[2][2][4];
            #pragma unroll
            for (int mt = 0; mt < 2; mt++)
                #pragma unroll
                for (int n = 0; n < 2; n++) {
                    #pragma unroll
                    for (int j = 0; j < 4; j++) s[mt][n][j] = 0.0f;
                    mma16816(s[mt][n], aq[mt][0], bk[n][0]);
                    mma16816(s[mt][n], aq[mt][1], bk[n][1]);
                }

            uint32_t ap[2][4];
            #pragma unroll
            for (int mt = 0; mt < 2; mt++) {
                float e0 = exp2f(s[mt][0][0]);
                float e1 = exp2f(s[mt][0][1]);
                float e2 = exp2f(s[mt][0][2]);
                float e3 = exp2f(s[mt][0][3]);
                float e4 = exp2f(s[mt][1][0]);
                float e5 = exp2f(s[mt][1][1]);
                float e6 = exp2f(s[mt][1][2]);
                float e7 = exp2f(s[mt][1][3]);
                lsum[mt][0] += (e0 + e1) + (e4 + e5);
                lsum[mt][1] += (e2 + e3) + (e6 + e7);
                ap[mt][0] = packbf2(e0, e1);
                ap[mt][1] = packbf2(e2, e3);
                ap[mt][2] = packbf2(e4, e5);
                ap[mt][3] = packbf2(e6, e7);
            }

            uint32_t bv[4][2];
            #pragma unroll
            for (int dn = 0; dn < 4; dn++)
                ldsm_x2_trans(bv[dn], smem_u32(
                    &Vt[(kb + half * 8 + r8) * ST_QK + dn * 8]));

            #pragma unroll
            for (int mt = 0; mt < 2; mt++)
                #pragma unroll
                for (int dn = 0; dn < 4; dn++)
                    mma16816(o[mt][dn], ap[mt], bv[dn]);
        }
        __syncthreads();
    }

    float linv[2][2];
    #pragma unroll
    for (int mt = 0; mt < 2; mt++)
        #pragma unroll
        for (int rh = 0; rh < 2; rh++) {
            float v = lsum[mt][rh];
            v += __shfl_xor_sync(0xFFFFFFFFu, v, 1);
            v += __shfl_xor_sync(0xFFFFFFFFu, v, 2);
            linv[mt][rh] = 1.0f / v;
        }

    float* Ap = g_A + (long)b * CH * NQ + (long)h * HD * NQ;
    const int g = lane >> 2, tg = lane & 3;
    #pragma unroll
    for (int mt = 0; mt < 2; mt++)
        #pragma unroll
        for (int dn = 0; dn < 4; dn++)
            #pragma unroll
            for (int rh = 0; rh < 2; rh++) {
                int n = q0 + wid * 32 + mt * 16 + rh * 8 + g;
                float sc = linv[mt][rh];
                int d0 = dn * 8 + tg * 2;
                Ap[(long)d0 * NQ + n]       = o[mt][dn][rh * 2 + 0] * sc;
                Ap[(long)(d0 + 1) * NQ + n] = o[mt][dn][rh * 2 + 1] * sc;
            }
}

// ---------------------------------------------------------------------------
// LayerNorm (known-good)
// ---------------------------------------------------------------------------
__global__ __launch_bounds__(256) void ln_kernel(
    const float* __restrict__ lnw, const float* __restrict__ lnb,
    float* __restrict__ out)
{
    const int b = blockIdx.y;
    const int n0 = blockIdx.x * 32;
    const int tid = threadIdx.x;

    __shared__ float s[CH][33];
    __shared__ float smu[32], srs[32];

    const float* Xp = g_O + (long)b * CH * NQ;
    const int cBase = tid >> 5;
    const int nn = tid & 31;

    #pragma unroll
    for (int i = 0; i < 32; i++) {
        int c = cBase + i * 8;
        s[c][nn] = Xp[(long)c * NQ + n0 + nn];
    }
    __syncthreads();

    int warp = tid >> 5, lane = tid & 31;
    for (int t = warp; t < 32; t += 8) {
        float sum = 0.0f, sq = 0.0f;
        #pragma unroll
        for (int j = 0; j < 8; j++) {
            float x = s[lane + j * 32][t];
            sum += x; sq += x * x;
        }
        #pragma unroll
        for (int off = 16; off > 0; off >>= 1) {
            sum += __shfl_xor_sync(0xFFFFFFFF, sum, off);
            sq  += __shfl_xor_sync(0xFFFFFFFF, sq, off);
        }
        if (lane == 0) {
            float mu = sum * (1.0f / CH);
            float var = sq * (1.0f / CH) - mu * mu;
            smu[t] = mu;
            srs[t] = rsqrtf(var + 1e-5f);
        }
    }
    __syncthreads();

    float mu = smu[nn], rs = srs[nn];
    #pragma unroll
    for (int i = 0; i < 32; i++) {
        int c = cBase + i * 8;
        float v = (s[c][nn] - mu) * rs * lnw[c] + lnb[c];
        out[(long)b * CH * NQ + (long)c * NQ + n0 + nn] = v;
    }
}

// ---------------------------------------------------------------------------
extern "C" void kernel_launch(void* const* d_in, const int* in_sizes, int n_in,
                              void* d_out, int out_size)
{
    const float* s3  = (const float*)d_in[0];
    const float* s4  = (const float*)d_in[1];
    const float* s5  = (const float*)d_in[2];
    const float* qw  = (const float*)d_in[3];
    const float* qb  = (const float*)d_in[4];
    const float* kw  = (const float*)d_in[5];
    const float* kb  = (const float*)d_in[6];
    const float* vw  = (const float*)d_in[7];
    const float* vb  = (const float*)d_in[8];
    const float* ow  = (const float*)d_in[9];
    const float* ob  = (const float*)d_in[10];
    const float* lnw = (const float*)d_in[11];
    const float* lnb = (const float*)d_in[12];
    float* out = (float*)d_out;

    // 32^-0.5 * log2(e)  (exp2-based softmax)
    const float qscale = 0.17677669529663689f * 1.4426950408889634f;

    // weights -> bf16 (order: q, k, v, o)
    wconv_kernel<<<dim3(CH * CH / 1024, 4), 256>>>(qw, kw, vw, ow);

    // fused QKV projections (single launch, 1280 CTAs)
    proj_qkv<<<dim3(320, 2, 2), 128>>>(s3, s4, s5, qb, kb, vb, qscale);

    // HMMA flash attention -> g_A fp32 [b][c][n]
    attn_mma_kernel<<<dim3(NQ / 256, NH, 2), 256>>>();

    // output projection + bias + residual -> g_O, then LN
    proj_o<<<dim3(128, 2, 2), 128>>>(ob, s3);
    ln_kernel<<<dim3(NQ / 32, 2), 256>>>(lnw, lnb, out);
}

// round 14
// speedup vs baseline: 7.2814x; 1.0803x over previous
#include <cuda_runtime.h>
#include <cuda_bf16.h>
#include <math.h>
#include <float.h>
#include <stdint.h>

#define CH 256
#define NQ 4096
#define NK 3072
#define NH 8
#define HD 32

// ---------------- scratch (no allocations allowed) ----------------
__device__ __nv_bfloat16 g_Ab[(size_t)2 * NQ * CH];       // attention out bf16 [b][n][c]
__device__ __nv_bfloat16 g_Qb[(size_t)2 * NH * NQ * HD];  // [b][h][n][d]
__device__ __nv_bfloat16 g_Kb[(size_t)2 * NH * NK * HD];  // [b][h][k][d]
__device__ __nv_bfloat16 g_Vb[(size_t)2 * NH * NK * HD];  // [b][h][k][d]
__device__ __nv_bfloat16 g_W[4 * CH * CH];                // bf16 weights: q,k,v,o

// ---------------- helpers (sm_80-level PTX only; no 'a' features) ----------
__device__ __forceinline__ uint32_t smem_u32(const void* p) {
    uint32_t a;
    asm("{ .reg .u64 t; cvta.to.shared.u64 t, %1; cvt.u32.u64 %0, t; }" : "=r"(a) : "l"(p));
    return a;
}
__device__ __forceinline__ void ldsm_x4(uint32_t* r, uint32_t addr) {
    asm volatile("ldmatrix.sync.aligned.m8n8.x4.shared.b16 {%0,%1,%2,%3}, [%4];"
        : "=r"(r[0]), "=r"(r[1]), "=r"(r[2]), "=r"(r[3]) : "r"(addr));
}
__device__ __forceinline__ void ldsm_x2(uint32_t* r, uint32_t addr) {
    asm volatile("ldmatrix.sync.aligned.m8n8.x2.shared.b16 {%0,%1}, [%2];"
        : "=r"(r[0]), "=r"(r[1]) : "r"(addr));
}
__device__ __forceinline__ void ldsm_x4_trans(uint32_t* r, uint32_t addr) {
    asm volatile("ldmatrix.sync.aligned.m8n8.x4.trans.shared.b16 {%0,%1,%2,%3}, [%4];"
        : "=r"(r[0]), "=r"(r[1]), "=r"(r[2]), "=r"(r[3]) : "r"(addr));
}
__device__ __forceinline__ void ldsm_x2_trans(uint32_t* r, uint32_t addr) {
    asm volatile("ldmatrix.sync.aligned.m8n8.x2.trans.shared.b16 {%0,%1}, [%2];"
        : "=r"(r[0]), "=r"(r[1]) : "r"(addr));
}
__device__ __forceinline__ void mma16816(float* c, const uint32_t* a, const uint32_t* b) {
    asm volatile(
        "mma.sync.aligned.m16n8k16.row.col.f32.bf16.bf16.f32 "
        "{%0,%1,%2,%3}, {%4,%5,%6,%7}, {%8,%9}, {%0,%1,%2,%3};"
        : "+f"(c[0]), "+f"(c[1]), "+f"(c[2]), "+f"(c[3])
        : "r"(a[0]), "r"(a[1]), "r"(a[2]), "r"(a[3]), "r"(b[0]), "r"(b[1]));
}
__device__ __forceinline__ uint32_t packbf2(float x, float y) {
    __nv_bfloat162 v = __floats2bfloat162_rn(x, y);
    return *reinterpret_cast<uint32_t*>(&v);
}
__device__ __forceinline__ float ex2f(float x) {   // guaranteed MUFU.EX2
    float y;
    asm("ex2.approx.ftz.f32 %0, %1;" : "=f"(y) : "f"(x));
    return y;
}
__device__ __forceinline__ void cp_async16(uint32_t dst, const void* src) {
    asm volatile("cp.async.cg.shared.global [%0], [%1], 16;" :: "r"(dst), "l"(src));
}
#define CP_COMMIT() asm volatile("cp.async.commit_group;" ::: "memory")
#define CP_WAIT0()  asm volatile("cp.async.wait_group 0;" ::: "memory")

// ---------------------------------------------------------------------------
// Weight fp32 -> bf16 (all 4 weight matrices in one launch)
// ---------------------------------------------------------------------------
__global__ __launch_bounds__(256) void wconv_kernel(
    const float* __restrict__ w0, const float* __restrict__ w1,
    const float* __restrict__ w2, const float* __restrict__ w3)
{
    const float* src[4] = {w0, w1, w2, w3};
    int t = blockIdx.y;
    int i = blockIdx.x * 256 + threadIdx.x;
    float4 v = reinterpret_cast<const float4*>(src[t])[i];
    uint2 u;
    u.x = packbf2(v.x, v.y);
    u.y = packbf2(v.z, v.w);
    reinterpret_cast<uint2*>(g_W + (size_t)t * CH * CH)[i] = u;
}

// ---------------------------------------------------------------------------
// Fused QKV projection (unchanged, proven). CTA = 128 thr, 32 tok x 128 outs.
// ---------------------------------------------------------------------------
#define STW 72
#define STX 40

__global__ __launch_bounds__(128) void proj_qkv(
    const float* __restrict__ s3, const float* __restrict__ s4,
    const float* __restrict__ s5,
    const float* __restrict__ qb2, const float* __restrict__ kb2,
    const float* __restrict__ vb2, float qsc)
{
    __shared__ __nv_bfloat16 Ws[128 * STW];
    __shared__ __nv_bfloat16 Xs[64 * STX];
    __shared__ float bs[128];

    const int i = blockIdx.x, oh = blockIdx.y, bb = blockIdx.z;

    const float* X; const float* bias; const __nv_bfloat16* Wsrc;
    __nv_bfloat16* dst; int ldx, outN, tokoff, tok0; float scale;
    if (i < 128)      { X = s3 + (long)bb * CH * NQ;   ldx = NQ;   tok0 = i * 32;
                        Wsrc = g_W;              bias = qb2; dst = g_Qb; outN = NQ; tokoff = 0;    scale = qsc; }
    else if (i < 192) { X = s4 + (long)bb * CH * 2048; ldx = 2048; tok0 = (i - 128) * 32;
                        Wsrc = g_W + CH * CH;    bias = kb2; dst = g_Kb; outN = NK; tokoff = 0;    scale = 1.0f; }
    else if (i < 224) { X = s5 + (long)bb * CH * 1024; ldx = 1024; tok0 = (i - 192) * 32;
                        Wsrc = g_W + CH * CH;    bias = kb2; dst = g_Kb; outN = NK; tokoff = 2048; scale = 1.0f; }
    else if (i < 288) { X = s4 + (long)bb * CH * 2048; ldx = 2048; tok0 = (i - 224) * 32;
                        Wsrc = g_W + 2 * CH * CH; bias = vb2; dst = g_Vb; outN = NK; tokoff = 0;    scale = 1.0f; }
    else              { X = s5 + (long)bb * CH * 1024; ldx = 1024; tok0 = (i - 288) * 32;
                        Wsrc = g_W + 2 * CH * CH; bias = vb2; dst = g_Vb; outN = NK; tokoff = 2048; scale = 1.0f; }

    const int tid = threadIdx.x, lane = tid & 31, w = tid >> 5;
    const int wt = (w & 1) * 16;
    const int wo = (w >> 1) * 64;
    const int r8 = lane & 7, mat = lane >> 3;

    bs[tid] = bias[oh * 128 + tid];

    float acc[8][4];
    #pragma unroll
    for (int a = 0; a < 8; a++)
        #pragma unroll
        for (int j = 0; j < 4; j++) acc[a][j] = 0.0f;

    #pragma unroll 1
    for (int c0 = 0; c0 < CH; c0 += 64) {
        __syncthreads();
        {
            const uint4* wg = reinterpret_cast<const uint4*>(
                Wsrc + (long)(oh * 128 + tid) * CH + c0);
            #pragma unroll
            for (int j = 0; j < 8; j++)
                *reinterpret_cast<uint4*>(&Ws[tid * STW + j * 8]) = wg[j];
        }
        {
            #pragma unroll
            for (int j = 0; j < 4; j++) {
                int idx = tid + j * 128;
                int c = idx >> 3, t4 = idx & 7;
                float4 v = *reinterpret_cast<const float4*>(
                    X + (long)(c0 + c) * ldx + tok0 + t4 * 4);
                uint2 u;
                u.x = packbf2(v.x, v.y);
                u.y = packbf2(v.z, v.w);
                *reinterpret_cast<uint2*>(&Xs[c * STX + t4 * 4]) = u;
            }
        }
        __syncthreads();

        #pragma unroll
        for (int ks = 0; ks < 4; ks++) {
            const int kk = ks * 16;
            uint32_t a[4];
            ldsm_x4_trans(a, smem_u32(
                &Xs[(kk + (mat >> 1) * 8 + r8) * STX + wt + (mat & 1) * 8]));
            #pragma unroll
            for (int nt = 0; nt < 4; nt++) {
                uint32_t bbf[4];
                ldsm_x4(bbf, smem_u32(
                    &Ws[(wo + nt * 16 + (mat >> 1) * 8 + r8) * STW + kk + (mat & 1) * 8]));
                mma16816(acc[nt * 2], a, bbf);
                mma16816(acc[nt * 2 + 1], a, bbf + 2);
            }
        }
    }

    const int g = lane >> 2, tg = lane & 3;
    #pragma unroll
    for (int n8 = 0; n8 < 8; n8++) {
        int ol = wo + n8 * 8 + tg * 2;
        int o = oh * 128 + ol;
        int h = o >> 5, d = o & 31;
        float b0 = bs[ol], b1 = bs[ol + 1];
        #pragma unroll
        for (int rh = 0; rh < 2; rh++) {
            int n = tokoff + tok0 + wt + rh * 8 + g;
            uint32_t pk = packbf2((acc[n8][rh * 2] + b0) * scale,
                                  (acc[n8][rh * 2 + 1] + b1) * scale);
            *reinterpret_cast<uint32_t*>(
                dst + (((long)(bb * NH + h) * outN + n) * HD + d)) = pk;
        }
    }
}

// ---------------------------------------------------------------------------
// HMMA flash attention; bare MUFU exp2; bf16 coalesced epilogue to g_Ab.
// ---------------------------------------------------------------------------
#define ST_QK 40

__global__ __launch_bounds__(256, 2) void attn_mma_kernel()
{
    __shared__ __nv_bfloat16 Qs[256 * ST_QK];
    __shared__ __nv_bfloat16 Ks[2][64 * ST_QK];
    __shared__ __nv_bfloat16 Vs[2][64 * ST_QK];

    const int b = blockIdx.z, h = blockIdx.y;
    const int q0 = blockIdx.x * 256;
    const int tid = threadIdx.x;
    const int wid = tid >> 5, lane = tid & 31;

    const __nv_bfloat16* Kg = g_Kb + (long)(b * NH + h) * NK * HD;
    const __nv_bfloat16* Vg = g_Vb + (long)(b * NH + h) * NK * HD;

    const int ldrow = tid >> 2, ldc = tid & 3;

    cp_async16(smem_u32(&Ks[0][ldrow * ST_QK + ldc * 8]),
               Kg + (long)ldrow * HD + ldc * 8);
    cp_async16(smem_u32(&Vs[0][ldrow * ST_QK + ldc * 8]),
               Vg + (long)ldrow * HD + ldc * 8);
    CP_COMMIT();

    {
        const uint4* qg = reinterpret_cast<const uint4*>(
            g_Qb + ((long)(b * NH + h) * NQ + q0) * HD);
        #pragma unroll
        for (int i = 0; i < 4; i++) {
            int idx = tid + i * 256;
            int row = idx >> 2, c = idx & 3;
            *reinterpret_cast<uint4*>(&Qs[row * ST_QK + c * 8]) = qg[idx];
        }
    }
    __syncthreads();

    uint32_t aq[2][2][4];
    {
        int mat = lane >> 3, r = lane & 7;
        #pragma unroll
        for (int mt = 0; mt < 2; mt++)
            #pragma unroll
            for (int ks = 0; ks < 2; ks++)
                ldsm_x4(aq[mt][ks], smem_u32(
                    &Qs[(wid * 32 + mt * 16 + (mat & 1) * 8 + r) * ST_QK
                        + ks * 16 + (mat >> 1) * 8]));
    }

    float o[2][4][4];
    #pragma unroll
    for (int mt = 0; mt < 2; mt++)
        #pragma unroll
        for (int dn = 0; dn < 4; dn++)
            #pragma unroll
            for (int j = 0; j < 4; j++) o[mt][dn][j] = 0.0f;
    float lsum[2][2] = {{0.0f, 0.0f}, {0.0f, 0.0f}};

    const int r8 = lane & 7;
    const int half = (lane >> 3) & 1;
    const int NT = NK / 64;

    #pragma unroll 1
    for (int t = 0; t < NT; t++) {
        CP_WAIT0();
        __syncthreads();
        if (t + 1 < NT) {
            const int nb = (t + 1) & 1;
            const long koff = (long)(t + 1) * 64 * HD;
            cp_async16(smem_u32(&Ks[nb][ldrow * ST_QK + ldc * 8]),
                       Kg + koff + (long)ldrow * HD + ldc * 8);
            cp_async16(smem_u32(&Vs[nb][ldrow * ST_QK + ldc * 8]),
                       Vg + koff + (long)ldrow * HD + ldc * 8);
            CP_COMMIT();
        }
        const __nv_bfloat16* Kt = Ks[t & 1];
        const __nv_bfloat16* Vt = Vs[t & 1];

        #pragma unroll
        for (int chnk = 0; chnk < 4; chnk++) {
            const int kb = chnk * 16;

            uint32_t bk[2][2][2];
            #pragma unroll
            for (int n = 0; n < 2; n++)
                #pragma unroll
                for (int ks = 0; ks < 2; ks++)
                    ldsm_x2(bk[n][ks], smem_u32(
                        &Kt[(kb + n * 8 + r8) * ST_QK + ks * 16 + half * 8]));

            float s[2][2][4];
            #pragma unroll
            for (int mt = 0; mt < 2; mt++)
                #pragma unroll
                for (int n = 0; n < 2; n++) {
                    #pragma unroll
                    for (int j = 0; j < 4; j++) s[mt][n][j] = 0.0f;
                    mma16816(s[mt][n], aq[mt][0], bk[n][0]);
                    mma16816(s[mt][n], aq[mt][1], bk[n][1]);
                }

            uint32_t ap[2][4];
            #pragma unroll
            for (int mt = 0; mt < 2; mt++) {
                float e0 = ex2f(s[mt][0][0]);
                float e1 = ex2f(s[mt][0][1]);
                float e2 = ex2f(s[mt][0][2]);
                float e3 = ex2f(s[mt][0][3]);
                float e4 = ex2f(s[mt][1][0]);
                float e5 = ex2f(s[mt][1][1]);
                float e6 = ex2f(s[mt][1][2]);
                float e7 = ex2f(s[mt][1][3]);
                lsum[mt][0] += (e0 + e1) + (e4 + e5);
                lsum[mt][1] += (e2 + e3) + (e6 + e7);
                ap[mt][0] = packbf2(e0, e1);
                ap[mt][1] = packbf2(e2, e3);
                ap[mt][2] = packbf2(e4, e5);
                ap[mt][3] = packbf2(e6, e7);
            }

            uint32_t bv[4][2];
            #pragma unroll
            for (int dn = 0; dn < 4; dn++)
                ldsm_x2_trans(bv[dn], smem_u32(
                    &Vt[(kb + half * 8 + r8) * ST_QK + dn * 8]));

            #pragma unroll
            for (int mt = 0; mt < 2; mt++)
                #pragma unroll
                for (int dn = 0; dn < 4; dn++)
                    mma16816(o[mt][dn], ap[mt], bv[dn]);
        }
        __syncthreads();
    }

    float linv[2][2];
    #pragma unroll
    for (int mt = 0; mt < 2; mt++)
        #pragma unroll
        for (int rh = 0; rh < 2; rh++) {
            float v = lsum[mt][rh];
            v += __shfl_xor_sync(0xFFFFFFFFu, v, 1);
            v += __shfl_xor_sync(0xFFFFFFFFu, v, 2);
            linv[mt][rh] = 1.0f / v;
        }

    // epilogue: bf16 [b][n][c], packed pairs along c (numerically free: o-proj
    // quantizes its A-operand to bf16 anyway)
    const int g = lane >> 2, tg = lane & 3;
    __nv_bfloat16* Ap = g_Ab + (long)b * NQ * CH;
    #pragma unroll
    for (int mt = 0; mt < 2; mt++)
        #pragma unroll
        for (int rh = 0; rh < 2; rh++) {
            int n = q0 + wid * 32 + mt * 16 + rh * 8 + g;
            float sc = linv[mt][rh];
            #pragma unroll
            for (int dn = 0; dn < 4; dn++) {
                int c = h * HD + dn * 8 + tg * 2;
                uint32_t pk = packbf2(o[mt][dn][rh * 2] * sc,
                                      o[mt][dn][rh * 2 + 1] * sc);
                *reinterpret_cast<uint32_t*>(Ap + (long)n * CH + c) = pk;
            }
        }
}

// ---------------------------------------------------------------------------
// Fused o-proj + bias + residual + LayerNorm. CTA = 32 tokens x all 256 outs,
// 256 thr. Phase A: HMMA GEMM from bf16 g_Ab (non-trans A frags) + bf16 W.
// Phase B: stage fp32 rows in smem (union over GEMM buffers), warp-reduce LN,
// coalesced write to out.
// ---------------------------------------------------------------------------
#define STA 264     // Xa row stride (bf16 elems): 528B -> ldsm bank-clean
#define STW2 40     // Ws row stride: 80B -> bank-clean
#define STG_LN 257  // LN stage row stride (fp32) -> column reads conflict-free
#define RAW_BYTES 37376   // max(Xa 16896 + Ws 20480, stage 32896)

__global__ __launch_bounds__(256) void proj_o_ln(
    const float* __restrict__ ob2, const float* __restrict__ res,
    const float* __restrict__ lnw, const float* __restrict__ lnb,
    float* __restrict__ out)
{
    __shared__ __align__(16) unsigned char raw[RAW_BYTES];
    __shared__ float bs[256];
    __shared__ float smu[32], srs[32];

    __nv_bfloat16* Xa = reinterpret_cast<__nv_bfloat16*>(raw);             // [32][STA]
    __nv_bfloat16* Ws = reinterpret_cast<__nv_bfloat16*>(raw + 16896);     // [256][STW2]
    float* stg = reinterpret_cast<float*>(raw);                            // [32][STG_LN]

    const int bb = blockIdx.y;
    const int tok0 = blockIdx.x * 32;
    const int tid = threadIdx.x, lane = tid & 31, w = tid >> 5;
    const int wt = (w & 1) * 16;      // token sub-tile
    const int wo = (w >> 1) * 64;     // out sub-tile (covers 256 across 4)
    const int r8 = lane & 7, mat = lane >> 3;

    bs[tid] = ob2[tid];

    // load Xa: [32 tok][256 c] bf16 (coalesced, 4 uint4/thread)
    {
        const uint4* Ag = reinterpret_cast<const uint4*>(
            g_Ab + ((long)bb * NQ + tok0) * CH);
        #pragma unroll
        for (int j = 0; j < 4; j++) {
            int idx = tid + j * 256;
            int row = idx >> 5, cc = idx & 31;
            *reinterpret_cast<uint4*>(&Xa[row * STA + cc * 8]) = Ag[idx];
        }
    }

    float acc[8][4];
    #pragma unroll
    for (int a = 0; a < 8; a++)
        #pragma unroll
        for (int j = 0; j < 4; j++) acc[a][j] = 0.0f;

    const __nv_bfloat16* Wsrc = g_W + 3 * CH * CH;

    #pragma unroll 1
    for (int c0 = 0; c0 < CH; c0 += 32) {
        __syncthreads();
        // Ws: thread row = out channel tid, 32 c = 4 uint4
        {
            const uint4* wg = reinterpret_cast<const uint4*>(
                Wsrc + (long)tid * CH + c0);
            #pragma unroll
            for (int j = 0; j < 4; j++)
                *reinterpret_cast<uint4*>(&Ws[tid * STW2 + j * 8]) = wg[j];
        }
        __syncthreads();

        #pragma unroll
        for (int ks = 0; ks < 2; ks++) {
            const int kk = ks * 16;
            uint32_t a[4];
            // A from row-major [tok][c]: non-trans (attention-Q pattern)
            ldsm_x4(a, smem_u32(
                &Xa[(wt + (mat & 1) * 8 + r8) * STA + c0 + kk + (mat >> 1) * 8]));
            #pragma unroll
            for (int nt = 0; nt < 4; nt++) {
                uint32_t bbf[4];
                ldsm_x4(bbf, smem_u32(
                    &Ws[(wo + nt * 16 + (mat >> 1) * 8 + r8) * STW2 + kk + (mat & 1) * 8]));
                mma16816(acc[nt * 2], a, bbf);
                mma16816(acc[nt * 2 + 1], a, bbf + 2);
            }
        }
    }

    // ---- Phase B: stage acc + bias + residual into fp32 smem rows ----
    __syncthreads();   // all reads of Xa/Ws done before overwrite
    const int g = lane >> 2, tg = lane & 3;
    #pragma unroll
    for (int n8 = 0; n8 < 8; n8++) {
        int ol = wo + n8 * 8 + tg * 2;   // c in [0,256)
        #pragma unroll
        for (int rh = 0; rh < 2; rh++) {
            int n = wt + rh * 8 + g;     // local token
            long i0 = ((long)bb * CH + ol) * NQ + tok0 + n;
            stg[n * STG_LN + ol]     = acc[n8][rh * 2]     + bs[ol]     + res[i0];
            stg[n * STG_LN + ol + 1] = acc[n8][rh * 2 + 1] + bs[ol + 1] + res[i0 + NQ];
        }
    }
    __syncthreads();

    // ---- LN reduce: warp w owns tokens w*4 .. w*4+3 ----
    #pragma unroll
    for (int tt = 0; tt < 4; tt++) {
        int t = w * 4 + tt;
        float sum = 0.0f, sq = 0.0f;
        #pragma unroll
        for (int j = 0; j < 8; j++) {
            float x = stg[t * STG_LN + lane + j * 32];
            sum += x; sq += x * x;
        }
        #pragma unroll
        for (int off = 16; off > 0; off >>= 1) {
            sum += __shfl_xor_sync(0xFFFFFFFFu, sum, off);
            sq  += __shfl_xor_sync(0xFFFFFFFFu, sq, off);
        }
        if (lane == 0) {
            float mu = sum * (1.0f / CH);
            float var = sq * (1.0f / CH) - mu * mu;
            smu[t] = mu;
            srs[t] = rsqrtf(var + 1e-5f);
        }
    }
    __syncthreads();

    // ---- write out [b][c][n], coalesced over n ----
    const int nn = tid & 31, cb = tid >> 5;
    float mu = smu[nn], rs = srs[nn];
    #pragma unroll
    for (int i = 0; i < 32; i++) {
        int c = cb + i * 8;
        float v = (stg[nn * STG_LN + c] - mu) * rs * lnw[c] + lnb[c];
        out[((long)bb * CH + c) * NQ + tok0 + nn] = v;
    }
}

// ---------------------------------------------------------------------------
extern "C" void kernel_launch(void* const* d_in, const int* in_sizes, int n_in,
                              void* d_out, int out_size)
{
    const float* s3  = (const float*)d_in[0];
    const float* s4  = (const float*)d_in[1];
    const float* s5  = (const float*)d_in[2];
    const float* qw  = (const float*)d_in[3];
    const float* qb  = (const float*)d_in[4];
    const float* kw  = (const float*)d_in[5];
    const float* kb  = (const float*)d_in[6];
    const float* vw  = (const float*)d_in[7];
    const float* vb  = (const float*)d_in[8];
    const float* ow  = (const float*)d_in[9];
    const float* ob  = (const float*)d_in[10];
    const float* lnw = (const float*)d_in[11];
    const float* lnb = (const float*)d_in[12];
    float* out = (float*)d_out;

    // 32^-0.5 * log2(e)  (exp2-based softmax)
    const float qscale = 0.17677669529663689f * 1.4426950408889634f;

    wconv_kernel<<<dim3(CH * CH / 1024, 4), 256>>>(qw, kw, vw, ow);
    proj_qkv<<<dim3(320, 2, 2), 128>>>(s3, s4, s5, qb, kb, vb, qscale);
    attn_mma_kernel<<<dim3(NQ / 256, NH, 2), 256>>>();
    proj_o_ln<<<dim3(NQ / 32, 2), 256>>>(ob, s3, lnw, lnb, out);
}